// round 9
// baseline (speedup 1.0000x reference)
#include <cuda_runtime.h>
#include <cuda_bf16.h>
#include <math.h>
#include <stdint.h>

// ---------------- problem constants ----------------
#define BB    4096
#define TT    32
#define VOCAB 10000
#define EE    300
#define HH    300
#define KSEG  320      // padded K per segment
#define KP2   640      // hi|lo storage columns
#define NP    1280     // 4H padded
#define MV    10112    // vocab padded to 64 (158*64)
#define NC    30       // K chunks of 32 (3 segments x 10)
#define MT    64
#define NT    128
#define NSTAGE 3
#define ROWB  80       // smem row stride bytes (32 cols * 2B + 16 pad)

// smem (dynamic) layout, bytes
#define SM_CAP   0          // 64 int
#define SM_LEN   256        // 64 int
#define SM_BIAS  512        // 128 float
#define SM_STAGE 1024
#define A_BYTES  (64 * ROWB)            // 5120
#define B_BYTES  (128 * ROWB)           // 10240
#define STAGE_BYTES (A_BYTES + B_BYTES) // 15360
#define SMEM_TOTAL (SM_STAGE + NSTAGE * STAGE_BYTES)   // 47104

// ---------------- device scratch ----------------
__device__ __nv_bfloat16 g_emb2[(size_t)MV * KP2];
__device__ __nv_bfloat16 g_wih2[(size_t)NP * KP2];
__device__ __nv_bfloat16 g_whh2[(size_t)NP * KP2];
__device__ float         g_bias[NP];
__device__ float         g_xproj[(size_t)MV * NP];
__device__ __nv_bfloat16 g_h2[2][(size_t)BB * KP2];
__device__ float         g_c[(size_t)BB * KSEG];
__device__ float         g_hlast[BB * HH];
__device__ float         g_wn[2 * HH];

// ---------------- PTX helpers (plain sm_80+ instructions only) ----------------
__device__ __forceinline__ uint32_t smem_u32(const void* p) {
    uint32_t a;
    asm("{ .reg .u64 t; cvta.to.shared.u64 t, %1; cvt.u32.u64 %0, t; }" : "=r"(a) : "l"(p));
    return a;
}
__device__ __forceinline__ void cp_async16(uint32_t s, const void* g) {
    asm volatile("cp.async.cg.shared.global [%0], [%1], 16;" :: "r"(s), "l"(g) : "memory");
}
__device__ __forceinline__ void cp_commit() {
    asm volatile("cp.async.commit_group;" ::: "memory");
}
__device__ __forceinline__ void cp_wait1() {
    asm volatile("cp.async.wait_group 1;" ::: "memory");
}
__device__ __forceinline__ void l2_prefetch(const void* g) {
    asm volatile("prefetch.global.L2 [%0];" :: "l"(g));
}
__device__ __forceinline__ void ldsm_x4(uint32_t* r, uint32_t addr) {
    asm volatile("ldmatrix.sync.aligned.m8n8.x4.shared.b16 {%0,%1,%2,%3}, [%4];"
                 : "=r"(r[0]), "=r"(r[1]), "=r"(r[2]), "=r"(r[3]) : "r"(addr));
}
__device__ __forceinline__ void mma16816(float* c, const uint32_t* a, const uint32_t* b) {
    asm volatile(
        "mma.sync.aligned.m16n8k16.row.col.f32.bf16.bf16.f32 "
        "{%0,%1,%2,%3}, {%4,%5,%6,%7}, {%8,%9}, {%0,%1,%2,%3};"
        : "+f"(c[0]), "+f"(c[1]), "+f"(c[2]), "+f"(c[3])
        : "r"(a[0]), "r"(a[1]), "r"(a[2]), "r"(a[3]), "r"(b[0]), "r"(b[1]));
}
__device__ __forceinline__ float fsig(float x)  { return 1.f / (1.f + __expf(-x)); }
__device__ __forceinline__ float ftanh(float x) { return 1.f - 2.f / (1.f + __expf(2.f * x)); }

// ---------------- prep: fp32 -> bf16 hi|lo split, gate interleave, zero state ----------------
__global__ void k_prep(const float* __restrict__ embed_w,
                       const float* __restrict__ W_ih,
                       const float* __restrict__ W_hh,
                       const float* __restrict__ b_ih,
                       const float* __restrict__ b_hh)
{
    const int stride = gridDim.x * blockDim.x;
    const int i0 = blockIdx.x * blockDim.x + threadIdx.x;

    for (size_t idx = i0; idx < (size_t)MV * KP2; idx += stride) {
        int r = idx / KP2, k2 = idx - (size_t)r * KP2;
        int k = (k2 >= KSEG) ? k2 - KSEG : k2;
        float v = (r < VOCAB && k < EE) ? embed_w[r * EE + k] : 0.f;
        __nv_bfloat16 hi = __float2bfloat16_rn(v);
        g_emb2[idx] = (k2 >= KSEG) ? __float2bfloat16_rn(v - __bfloat162float(hi)) : hi;
    }
    for (size_t idx = i0; idx < (size_t)NP * KP2; idx += stride) {
        int n = idx / KP2, k2 = idx - (size_t)n * KP2;
        int k = (k2 >= KSEG) ? k2 - KSEG : k2;
        int gs = n & 3, u = n >> 2;
        float vi = 0.f, vh = 0.f;
        if (u < HH && k < EE) {
            int s = (gs * HH + u) * EE + k;
            vi = W_ih[s];
            vh = W_hh[s];
        }
        __nv_bfloat16 hi_i = __float2bfloat16_rn(vi);
        __nv_bfloat16 hi_h = __float2bfloat16_rn(vh);
        if (k2 >= KSEG) {
            g_wih2[idx] = __float2bfloat16_rn(vi - __bfloat162float(hi_i));
            g_whh2[idx] = __float2bfloat16_rn(vh - __bfloat162float(hi_h));
        } else {
            g_wih2[idx] = hi_i;
            g_whh2[idx] = hi_h;
        }
    }
    for (int n = i0; n < NP; n += stride) {
        int gs = n & 3, u = n >> 2;
        g_bias[n] = (u < HH) ? (b_ih[gs * HH + u] + b_hh[gs * HH + u]) : 0.f;
    }
    for (size_t idx = i0; idx < (size_t)BB * KP2; idx += stride) {
        g_h2[0][idx] = __float2bfloat16_rn(0.f);
        g_h2[1][idx] = __float2bfloat16_rn(0.f);
    }
    for (size_t idx = i0; idx < (size_t)BB * KSEG; idx += stride)
        g_c[idx] = 0.f;
}

__global__ void k_prep_cls(const float* __restrict__ cls_v,
                           const float* __restrict__ cls_g)
{
    int w = threadIdx.x >> 5;
    int lane = threadIdx.x & 31;
    if (w >= 2) return;
    float s = 0.f;
    for (int k = lane; k < HH; k += 32) {
        float v = cls_v[w * HH + k];
        s += v * v;
    }
    #pragma unroll
    for (int o = 16; o; o >>= 1) s += __shfl_xor_sync(0xffffffff, s, o);
    float scale = cls_g[w] / sqrtf(s);
    for (int k = lane; k < HH; k += 32)
        g_wn[w * HH + k] = cls_v[w * HH + k] * scale;
}

// ---------------- HMMA GEMM: C[64,128] = A[64,960] x B[128,960]^T ----------------
// Extended K: A chunks [hi|lo|hi], B chunks [hi|hi|lo]
// 128 threads, 4 warps (2m x 2n), warp tile 32x64; 4 CTAs/SM.
// MODE 0: A=g_emb2, B=g_wih2 -> store g_xproj
// MODE 1: A=g_h2[parity], B=g_whh2 -> fused LSTM epilogue
template <int MODE>
__global__ void __launch_bounds__(128, 4) k_tgemm(int t, int parity,
                                                  const int* __restrict__ cap,
                                                  const int* __restrict__ cap_len)
{
    extern __shared__ char smem[];
    const uint32_t sb = smem_u32(smem);
    const int tid = threadIdx.x;
    const int wid = tid >> 5;
    const int lane = tid & 31;
    const int wm = wid >> 1;         // 0..1 : 32-row slice
    const int wn = wid & 1;          // 0..1 : 64-col slice
    const int m0 = blockIdx.y * MT;
    const int n0 = blockIdx.x * NT;

    const __nv_bfloat16* Ag = (MODE == 0) ? g_emb2 : g_h2[parity];
    const __nv_bfloat16* Bg = (MODE == 0) ? g_wih2 : g_whh2;

    if (MODE == 1) {
        if (tid < 64) {
            const int tok = cap[(m0 + tid) * TT + t];
            ((int*)(smem + SM_CAP))[tid] = tok;
            ((int*)(smem + SM_LEN))[tid] = cap_len[m0 + tid];
            const char* pr = (const char*)(g_xproj + (size_t)tok * NP + n0);
            l2_prefetch(pr);
            l2_prefetch(pr + 128);
            l2_prefetch(pr + 256);
            l2_prefetch(pr + 384);
        } else {
            ((float*)(smem + SM_BIAS))[tid - 64] = g_bias[n0 + tid - 64];
            ((float*)(smem + SM_BIAS))[tid]      = g_bias[n0 + tid];
        }
    }

    // loader geometry per chunk of 32 k:
    //   A = 64 rows x 64B  : 2 units of 16B per thread (row = tid>>1)
    //   B = 128 rows x 64B : 4 units = one full row per thread (row = tid)
    const int a_row = tid >> 1;
    const int a_cu  = (tid & 1) * 2;

    uint32_t stA[NSTAGE], stB[NSTAGE];
    #pragma unroll
    for (int s = 0; s < NSTAGE; s++) {
        stA[s] = sb + SM_STAGE + s * STAGE_BYTES;
        stB[s] = stA[s] + A_BYTES;
    }

    auto issue_chunk = [&](int c) {
        if (c < NC) {
            const int stage = c % 3;
            const int seg = c / 10, within = (c - seg * 10) * 32;
            const int aoff = ((seg == 1) ? KSEG : 0) + within;
            const int boff = ((seg == 2) ? KSEG : 0) + within;
            const __nv_bfloat16* ap = Ag + (size_t)(m0 + a_row) * KP2 + aoff + a_cu * 8;
            const __nv_bfloat16* bp = Bg + (size_t)(n0 + tid) * KP2 + boff;
            const uint32_t sa  = stA[stage] + a_row * ROWB + a_cu * 16;
            const uint32_t sbm = stB[stage] + tid * ROWB;
            cp_async16(sa, ap);
            cp_async16(sa + 16, ap + 8);
            #pragma unroll
            for (int i = 0; i < 4; i++)
                cp_async16(sbm + i * 16, bp + i * 8);
        }
        cp_commit();
    };

    float acc[2][8][4];
    #pragma unroll
    for (int i = 0; i < 2; i++)
        #pragma unroll
        for (int j = 0; j < 8; j++)
            #pragma unroll
            for (int e = 0; e < 4; e++) acc[i][j][e] = 0.f;

    // ldmatrix addressing
    const uint32_t a_lrow = (uint32_t)(wm * 32 + (lane & 15)) * ROWB;
    const uint32_t a_kofs = (uint32_t)((lane >> 4) * 16);
    // B x4: covers two adjacent n8 tiles; lanes16-31 -> +8 rows
    const uint32_t b_lrow = (uint32_t)(wn * 64 + ((lane >> 4) & 1) * 8 + (lane & 7)) * ROWB;
    const uint32_t b_kofs = (uint32_t)(((lane >> 3) & 1) * 16);

    issue_chunk(0);
    issue_chunk(1);

    for (int c = 0; c < NC; c++) {
        cp_wait1();
        __syncthreads();
        issue_chunk(c + 2);                 // into stage freed last iteration
        const int stage = c % 3;
        const uint32_t sA = stA[stage], sB = stB[stage];
        #pragma unroll
        for (int k16 = 0; k16 < 2; k16++) {
            uint32_t a[2][4], b[4][4];
            #pragma unroll
            for (int i = 0; i < 2; i++)
                ldsm_x4(a[i], sA + a_lrow + i * 16 * ROWB + k16 * 32 + a_kofs);
            #pragma unroll
            for (int j2 = 0; j2 < 4; j2++)
                ldsm_x4(b[j2], sB + b_lrow + j2 * 16 * ROWB + k16 * 32 + b_kofs);
            #pragma unroll
            for (int i = 0; i < 2; i++)
                #pragma unroll
                for (int j2 = 0; j2 < 4; j2++) {
                    mma16816(acc[i][2 * j2 + 0], a[i], &b[j2][0]);
                    mma16816(acc[i][2 * j2 + 1], a[i], &b[j2][2]);
                }
        }
    }

    // ---------------- epilogue ----------------
    const int lr_base = wm * 32 + (lane >> 2);
    const int nl_base = wn * 64 + 2 * (lane & 3);
    const bool odd = lane & 1;

    if (MODE == 0) {
        #pragma unroll
        for (int i = 0; i < 2; i++) {
            const int r0 = m0 + lr_base + i * 16;
            #pragma unroll
            for (int j = 0; j < 8; j++) {
                const int ng = n0 + nl_base + j * 8;
                *(float2*)(g_xproj + (size_t)r0 * NP + ng) = make_float2(acc[i][j][0], acc[i][j][1]);
                *(float2*)(g_xproj + (size_t)(r0 + 8) * NP + ng) = make_float2(acc[i][j][2], acc[i][j][3]);
            }
        }
    } else {
        const int* s_cap = (const int*)(smem + SM_CAP);
        const int* s_len = (const int*)(smem + SM_LEN);
        const float* s_bias = (const float*)(smem + SM_BIAS);
        __nv_bfloat16* hout = g_h2[parity ^ 1];

        #pragma unroll
        for (int i = 0; i < 2; i++) {
            const int lr0 = lr_base + i * 16;
            const int r0 = m0 + lr0, r1 = r0 + 8;
            const int tok0 = s_cap[lr0], tok1 = s_cap[lr0 + 8];
            const int  rme    = odd ? r1 : r0;
            const bool lastme = odd ? (t == s_len[lr0 + 8] - 1) : (t == s_len[lr0] - 1);
            #pragma unroll
            for (int j = 0; j < 8; j++) {
                const int nl = nl_base + j * 8;
                const int ng = n0 + nl;
                const float2 x0 = *(const float2*)(g_xproj + (size_t)tok0 * NP + ng);
                const float2 x1 = *(const float2*)(g_xproj + (size_t)tok1 * NP + ng);
                const float2 bi = *(const float2*)(s_bias + nl);
                float v0 = acc[i][j][0] + x0.x + bi.x;
                float v1 = acc[i][j][1] + x0.y + bi.y;
                float v2 = acc[i][j][2] + x1.x + bi.x;
                float v3 = acc[i][j][3] + x1.y + bi.y;
                // partner exchange: even lane owns (i,f), odd owns (g,o)
                float o0 = __shfl_xor_sync(0xffffffff, v0, 1);
                float o1 = __shfl_xor_sync(0xffffffff, v1, 1);
                float o2 = __shfl_xor_sync(0xffffffff, v2, 1);
                float o3 = __shfl_xor_sync(0xffffffff, v3, 1);
                float gi, gf, gg, go;
                if (!odd) { gi = v0; gf = v1; gg = o0; go = o1; }   // row0
                else      { gi = o2; gf = o3; gg = v2; go = v3; }   // row1
                const int u = (ng - (odd ? 2 : 0)) >> 2;            // hidden unit
                float I = fsig(gi), F = fsig(gf), G = ftanh(gg), O = fsig(go);
                float cn = F * g_c[(size_t)rme * KSEG + u] + I * G;
                float hn = O * ftanh(cn);
                g_c[(size_t)rme * KSEG + u] = cn;
                __nv_bfloat16 hb = __float2bfloat16_rn(hn);
                hout[(size_t)rme * KP2 + u] = hb;
                hout[(size_t)rme * KP2 + KSEG + u] =
                    __float2bfloat16_rn(hn - __bfloat162float(hb));
                if (lastme && u < HH) g_hlast[rme * HH + u] = hn;
            }
        }
    }
}

// ---------------- classifier ----------------
__global__ void k_cls(const float* __restrict__ cls_b, float* __restrict__ out)
{
    int warp = (blockIdx.x * blockDim.x + threadIdx.x) >> 5;
    int lane = threadIdx.x & 31;
    if (warp >= BB) return;
    float s0 = 0.f, s1 = 0.f;
    for (int k = lane; k < HH; k += 32) {
        float hv = g_hlast[warp * HH + k];
        s0 += hv * g_wn[k];
        s1 += hv * g_wn[HH + k];
    }
    #pragma unroll
    for (int o = 16; o; o >>= 1) {
        s0 += __shfl_xor_sync(0xffffffff, s0, o);
        s1 += __shfl_xor_sync(0xffffffff, s1, o);
    }
    if (lane == 0) {
        out[warp * 2 + 0] = s0 + cls_b[0];
        out[warp * 2 + 1] = s1 + cls_b[1];
    }
}

extern "C" void kernel_launch(void* const* d_in, const int* in_sizes, int n_in,
                              void* d_out, int out_size)
{
    const int*   cap     = (const int*)d_in[0];
    const int*   cap_len = (const int*)d_in[1];
    const float* embed_w = (const float*)d_in[2];
    const float* W_ih    = (const float*)d_in[3];
    const float* W_hh    = (const float*)d_in[4];
    const float* b_ih    = (const float*)d_in[5];
    const float* b_hh    = (const float*)d_in[6];
    const float* cls_v   = (const float*)d_in[7];
    const float* cls_g   = (const float*)d_in[8];
    const float* cls_b   = (const float*)d_in[9];
    float* out = (float*)d_out;

    cudaFuncSetAttribute(k_tgemm<0>, cudaFuncAttributeMaxDynamicSharedMemorySize, SMEM_TOTAL);
    cudaFuncSetAttribute(k_tgemm<1>, cudaFuncAttributeMaxDynamicSharedMemorySize, SMEM_TOTAL);

    k_prep<<<2048, 256>>>(embed_w, W_ih, W_hh, b_ih, b_hh);
    k_prep_cls<<<1, 64>>>(cls_v, cls_g);

    {   // x_proj = emb @ W_ih^T
        dim3 grid(NP / NT, MV / MT);   // (10, 158)
        k_tgemm<0><<<grid, 128, SMEM_TOTAL>>>(0, 0, nullptr, nullptr);
    }
    {   // 32 fused recurrent steps
        dim3 grid(NP / NT, BB / MT);   // (10, 64) = 640 CTAs, 4 per SM
        for (int t = 0; t < TT; t++)
            k_tgemm<1><<<grid, 128, SMEM_TOTAL>>>(t, t & 1, cap, cap_len);
    }
    k_cls<<<512, 256>>>(cls_b, out);
}

// round 10
// speedup vs baseline: 1.4575x; 1.4575x over previous
#include <cuda_runtime.h>
#include <cuda_fp16.h>
#include <math.h>
#include <stdint.h>

// ---------------- problem constants ----------------
#define BB    4096
#define TT    32
#define VOCAB 10000
#define EE    300
#define HH    300
#define KSEG  320      // padded K per segment
#define KP2   640      // A-side hi|lo storage columns
#define NP    1280     // 4H padded
#define MV    10112    // vocab padded to 128
#define NC    20       // K chunks of 32 (2 segments x 10)
#define MT    128
#define NT    128
#define NSTAGE 4
#define ROWB  80       // smem row stride bytes (32 cols * 2B + 16 pad)

// smem (dynamic) layout, bytes
#define SM_CAP   0          // 128 int
#define SM_LEN   512        // 128 int
#define SM_BIAS  1024       // 128 float
#define SM_STAGE 2048       // 4 stages x (A 10240 + B 10240)
#define STAGE_BYTES 20480
#define SMEM_TOTAL (SM_STAGE + NSTAGE * STAGE_BYTES)   // 83968

// ---------------- device scratch ----------------
__device__ __half g_embA[(size_t)MV * KP2];      // emb hi|lo (fp16)
__device__ __half g_wihB[(size_t)NP * KSEG];     // W_ih hi only, gate-interleaved
__device__ __half g_whhB[(size_t)NP * KSEG];     // W_hh hi only, gate-interleaved
__device__ float  g_bias[NP];
__device__ float  g_xproj[(size_t)MV * NP];
__device__ __half g_h2[2][(size_t)BB * KP2];     // hidden hi|lo, double buffer
__device__ float  g_c[(size_t)BB * KSEG];
__device__ float  g_hlast[BB * HH];
__device__ float  g_wn[2 * HH];

// ---------------- PTX helpers (plain sm_80+ instructions only) ----------------
__device__ __forceinline__ uint32_t smem_u32(const void* p) {
    uint32_t a;
    asm("{ .reg .u64 t; cvta.to.shared.u64 t, %1; cvt.u32.u64 %0, t; }" : "=r"(a) : "l"(p));
    return a;
}
__device__ __forceinline__ void cp_async16(uint32_t s, const void* g) {
    asm volatile("cp.async.cg.shared.global [%0], [%1], 16;" :: "r"(s), "l"(g) : "memory");
}
__device__ __forceinline__ void cp_commit() {
    asm volatile("cp.async.commit_group;" ::: "memory");
}
__device__ __forceinline__ void cp_wait2() {
    asm volatile("cp.async.wait_group 2;" ::: "memory");
}
__device__ __forceinline__ void l2_prefetch(const void* g) {
    asm volatile("prefetch.global.L2 [%0];" :: "l"(g));
}
__device__ __forceinline__ void ldsm_x4(uint32_t* r, uint32_t addr) {
    asm volatile("ldmatrix.sync.aligned.m8n8.x4.shared.b16 {%0,%1,%2,%3}, [%4];"
                 : "=r"(r[0]), "=r"(r[1]), "=r"(r[2]), "=r"(r[3]) : "r"(addr));
}
__device__ __forceinline__ void ldsm_x2(uint32_t* r, uint32_t addr) {
    asm volatile("ldmatrix.sync.aligned.m8n8.x2.shared.b16 {%0,%1}, [%2];"
                 : "=r"(r[0]), "=r"(r[1]) : "r"(addr));
}
__device__ __forceinline__ void mma16816(float* c, const uint32_t* a, const uint32_t* b) {
    asm volatile(
        "mma.sync.aligned.m16n8k16.row.col.f32.f16.f16.f32 "
        "{%0,%1,%2,%3}, {%4,%5,%6,%7}, {%8,%9}, {%0,%1,%2,%3};"
        : "+f"(c[0]), "+f"(c[1]), "+f"(c[2]), "+f"(c[3])
        : "r"(a[0]), "r"(a[1]), "r"(a[2]), "r"(a[3]), "r"(b[0]), "r"(b[1]));
}
__device__ __forceinline__ float fsig(float x)  { return 1.f / (1.f + __expf(-x)); }
__device__ __forceinline__ float ftanh(float x) { return 1.f - 2.f / (1.f + __expf(2.f * x)); }

// ---------------- prep: fp32 -> fp16 hi|lo (A) / hi (B), gate interleave ----------------
__global__ void k_prep(const float* __restrict__ embed_w,
                       const float* __restrict__ W_ih,
                       const float* __restrict__ W_hh,
                       const float* __restrict__ b_ih,
                       const float* __restrict__ b_hh)
{
    const int stride = gridDim.x * blockDim.x;
    const int i0 = blockIdx.x * blockDim.x + threadIdx.x;

    for (size_t idx = i0; idx < (size_t)MV * KP2; idx += stride) {
        int r = idx / KP2, k2 = idx - (size_t)r * KP2;
        int k = (k2 >= KSEG) ? k2 - KSEG : k2;
        float v = (r < VOCAB && k < EE) ? embed_w[r * EE + k] : 0.f;
        __half hi = __float2half_rn(v);
        g_embA[idx] = (k2 >= KSEG) ? __float2half_rn(v - __half2float(hi)) : hi;
    }
    for (size_t idx = i0; idx < (size_t)NP * KSEG; idx += stride) {
        int n = idx / KSEG, k = idx - (size_t)n * KSEG;
        int gs = n & 3, u = n >> 2;
        float vi = 0.f, vh = 0.f;
        if (u < HH && k < EE) {
            int s = (gs * HH + u) * EE + k;
            vi = W_ih[s];
            vh = W_hh[s];
        }
        g_wihB[idx] = __float2half_rn(vi);
        g_whhB[idx] = __float2half_rn(vh);
    }
    for (int n = i0; n < NP; n += stride) {
        int gs = n & 3, u = n >> 2;
        g_bias[n] = (u < HH) ? (b_ih[gs * HH + u] + b_hh[gs * HH + u]) : 0.f;
    }
    for (size_t idx = i0; idx < (size_t)BB * KP2; idx += stride) {
        g_h2[0][idx] = __float2half_rn(0.f);
        g_h2[1][idx] = __float2half_rn(0.f);
    }
    for (size_t idx = i0; idx < (size_t)BB * KSEG; idx += stride)
        g_c[idx] = 0.f;
}

__global__ void k_prep_cls(const float* __restrict__ cls_v,
                           const float* __restrict__ cls_g)
{
    int w = threadIdx.x >> 5;
    int lane = threadIdx.x & 31;
    if (w >= 2) return;
    float s = 0.f;
    for (int k = lane; k < HH; k += 32) {
        float v = cls_v[w * HH + k];
        s += v * v;
    }
    #pragma unroll
    for (int o = 16; o; o >>= 1) s += __shfl_xor_sync(0xffffffff, s, o);
    float scale = cls_g[w] / sqrtf(s);
    for (int k = lane; k < HH; k += 32)
        g_wn[w * HH + k] = cls_v[w * HH + k] * scale;
}

// ---------------- HMMA GEMM: C[128,128] = A[128,640] x B_ext[128,640]^T ----------------
// A chunks: seg0 = hi, seg1 = lo.  B chunks: hi for both segments.
// MODE 0: A=g_embA, B=g_wihB -> store g_xproj
// MODE 1: A=g_h2[parity], B=g_whhB -> fused LSTM epilogue
template <int MODE>
__global__ void __launch_bounds__(256, 2) k_tgemm(int t, int parity,
                                                  const int* __restrict__ cap,
                                                  const int* __restrict__ cap_len)
{
    extern __shared__ char smem[];
    const uint32_t sb = smem_u32(smem);
    const int tid = threadIdx.x;
    const int wid = tid >> 5;
    const int lane = tid & 31;
    const int wm = wid >> 2;         // 0..1 : 64-row slice
    const int wn = wid & 3;          // 0..3 : 32-col slice
    const int m0 = blockIdx.y * MT;
    const int n0 = blockIdx.x * NT;

    const __half* Ag = (MODE == 0) ? g_embA : g_h2[parity];
    const __half* Bg = (MODE == 0) ? g_wihB : g_whhB;

    if (MODE == 1) {
        if (tid < 128) {
            const int tok = cap[(m0 + tid) * TT + t];
            ((int*)(smem + SM_CAP))[tid] = tok;
            ((int*)(smem + SM_LEN))[tid] = cap_len[m0 + tid];
            // warm L2 for the epilogue gather (this CTA's 128-col slice of row tok)
            const char* pr = (const char*)(g_xproj + (size_t)tok * NP + n0);
            l2_prefetch(pr);
            l2_prefetch(pr + 128);
            l2_prefetch(pr + 256);
            l2_prefetch(pr + 384);
        } else {
            ((float*)(smem + SM_BIAS))[tid - 128] = g_bias[n0 + tid - 128];
        }
    }

    // loader: per chunk A = 128x32 fp16 (128 rows x 4 x 16B), B same; 2 units/thread.
    const int a_row = tid >> 1;
    const int a_cu  = (tid & 1) * 2;

    uint32_t stA[NSTAGE], stB[NSTAGE];
    #pragma unroll
    for (int s = 0; s < NSTAGE; s++) {
        stA[s] = sb + SM_STAGE + s * STAGE_BYTES;
        stB[s] = stA[s] + 10240;
    }

    auto issue_chunk = [&](int c) {
        if (c < NC) {
            const int stage = c & 3;
            const int seg = c / 10, within = (c - seg * 10) * 32;
            const int aoff = seg * KSEG + within;
            const int boff = within;                       // B: hi for both segments
            const __half* ap = Ag + (size_t)(m0 + a_row) * KP2 + aoff + a_cu * 8;
            const __half* bp = Bg + (size_t)(n0 + a_row) * KSEG + boff + a_cu * 8;
            const uint32_t sa  = stA[stage] + a_row * ROWB + a_cu * 16;
            const uint32_t sbm = stB[stage] + a_row * ROWB + a_cu * 16;
            cp_async16(sa, ap);
            cp_async16(sa + 16, ap + 8);
            cp_async16(sbm, bp);
            cp_async16(sbm + 16, bp + 8);
        }
        cp_commit();
    };

    float acc[4][4][4];
    #pragma unroll
    for (int i = 0; i < 4; i++)
        #pragma unroll
        for (int j = 0; j < 4; j++)
            #pragma unroll
            for (int e = 0; e < 4; e++) acc[i][j][e] = 0.f;

    const uint32_t a_lrow = (uint32_t)(wm * 64 + (lane & 15)) * ROWB;
    const uint32_t a_kofs = (uint32_t)((lane >> 4) * 16);
    const uint32_t b_lrow = (uint32_t)(wn * 32 + (lane & 7)) * ROWB;
    const uint32_t b_kofs = (uint32_t)(((lane >> 3) & 1) * 16);

    issue_chunk(0);
    issue_chunk(1);
    issue_chunk(2);

    for (int c = 0; c < NC; c++) {
        cp_wait2();
        __syncthreads();
        issue_chunk(c + 3);                 // into stage freed by previous iteration
        const int stage = c & 3;
        const uint32_t sA = stA[stage], sB = stB[stage];
        #pragma unroll
        for (int k16 = 0; k16 < 2; k16++) {
            uint32_t a[4][4], b[4][2];
            #pragma unroll
            for (int i = 0; i < 4; i++)
                ldsm_x4(a[i], sA + a_lrow + i * 16 * ROWB + k16 * 32 + a_kofs);
            #pragma unroll
            for (int j = 0; j < 4; j++)
                ldsm_x2(b[j], sB + b_lrow + j * 8 * ROWB + k16 * 32 + b_kofs);
            #pragma unroll
            for (int i = 0; i < 4; i++)
                #pragma unroll
                for (int j = 0; j < 4; j++)
                    mma16816(acc[i][j], a[i], b[j]);
        }
    }

    // ---------------- epilogue ----------------
    const int lr_base = wm * 64 + (lane >> 2);
    const int nl_base = wn * 32 + 2 * (lane & 3);
    const bool odd = lane & 1;

    if (MODE == 0) {
        #pragma unroll
        for (int i = 0; i < 4; i++) {
            const int r0 = m0 + lr_base + i * 16;
            #pragma unroll
            for (int j = 0; j < 4; j++) {
                const int ng = n0 + nl_base + j * 8;
                *(float2*)(g_xproj + (size_t)r0 * NP + ng) = make_float2(acc[i][j][0], acc[i][j][1]);
                *(float2*)(g_xproj + (size_t)(r0 + 8) * NP + ng) = make_float2(acc[i][j][2], acc[i][j][3]);
            }
        }
    } else {
        const int* s_cap = (const int*)(smem + SM_CAP);
        const int* s_len = (const int*)(smem + SM_LEN);
        const float* s_bias = (const float*)(smem + SM_BIAS);
        __half* hout = g_h2[parity ^ 1];

        #pragma unroll
        for (int i = 0; i < 4; i++) {
            const int lr0 = lr_base + i * 16;
            const int r0 = m0 + lr0, r1 = r0 + 8;
            const int tok0 = s_cap[lr0], tok1 = s_cap[lr0 + 8];
            const int  rme    = odd ? r1 : r0;
            const bool lastme = odd ? (t == s_len[lr0 + 8] - 1) : (t == s_len[lr0] - 1);
            #pragma unroll
            for (int j = 0; j < 4; j++) {
                const int nl = nl_base + j * 8;
                const int ng = n0 + nl;
                const float2 x0 = *(const float2*)(g_xproj + (size_t)tok0 * NP + ng);
                const float2 x1 = *(const float2*)(g_xproj + (size_t)tok1 * NP + ng);
                const float2 bi = *(const float2*)(s_bias + nl);
                float v0 = acc[i][j][0] + x0.x + bi.x;
                float v1 = acc[i][j][1] + x0.y + bi.y;
                float v2 = acc[i][j][2] + x1.x + bi.x;
                float v3 = acc[i][j][3] + x1.y + bi.y;
                // partner exchange: even lane owns (i,f), odd owns (g,o)
                float o0 = __shfl_xor_sync(0xffffffff, v0, 1);
                float o1 = __shfl_xor_sync(0xffffffff, v1, 1);
                float o2 = __shfl_xor_sync(0xffffffff, v2, 1);
                float o3 = __shfl_xor_sync(0xffffffff, v3, 1);
                float gi, gf, gg, go;
                if (!odd) { gi = v0; gf = v1; gg = o0; go = o1; }   // row0
                else      { gi = o2; gf = o3; gg = v2; go = v3; }   // row1
                const int u = (ng - (odd ? 2 : 0)) >> 2;            // hidden unit
                float I = fsig(gi), F = fsig(gf), G = ftanh(gg), O = fsig(go);
                float cn = F * g_c[(size_t)rme * KSEG + u] + I * G;
                float hn = O * ftanh(cn);
                g_c[(size_t)rme * KSEG + u] = cn;
                __half hb = __float2half_rn(hn);
                hout[(size_t)rme * KP2 + u] = hb;
                hout[(size_t)rme * KP2 + KSEG + u] =
                    __float2half_rn(hn - __half2float(hb));
                if (lastme && u < HH) g_hlast[rme * HH + u] = hn;
            }
        }
    }
}

// ---------------- classifier ----------------
__global__ void k_cls(const float* __restrict__ cls_b, float* __restrict__ out)
{
    int warp = (blockIdx.x * blockDim.x + threadIdx.x) >> 5;
    int lane = threadIdx.x & 31;
    if (warp >= BB) return;
    float s0 = 0.f, s1 = 0.f;
    for (int k = lane; k < HH; k += 32) {
        float hv = g_hlast[warp * HH + k];
        s0 += hv * g_wn[k];
        s1 += hv * g_wn[HH + k];
    }
    #pragma unroll
    for (int o = 16; o; o >>= 1) {
        s0 += __shfl_xor_sync(0xffffffff, s0, o);
        s1 += __shfl_xor_sync(0xffffffff, s1, o);
    }
    if (lane == 0) {
        out[warp * 2 + 0] = s0 + cls_b[0];
        out[warp * 2 + 1] = s1 + cls_b[1];
    }
}

extern "C" void kernel_launch(void* const* d_in, const int* in_sizes, int n_in,
                              void* d_out, int out_size)
{
    const int*   cap     = (const int*)d_in[0];
    const int*   cap_len = (const int*)d_in[1];
    const float* embed_w = (const float*)d_in[2];
    const float* W_ih    = (const float*)d_in[3];
    const float* W_hh    = (const float*)d_in[4];
    const float* b_ih    = (const float*)d_in[5];
    const float* b_hh    = (const float*)d_in[6];
    const float* cls_v   = (const float*)d_in[7];
    const float* cls_g   = (const float*)d_in[8];
    const float* cls_b   = (const float*)d_in[9];
    float* out = (float*)d_out;

    cudaFuncSetAttribute(k_tgemm<0>, cudaFuncAttributeMaxDynamicSharedMemorySize, SMEM_TOTAL);
    cudaFuncSetAttribute(k_tgemm<1>, cudaFuncAttributeMaxDynamicSharedMemorySize, SMEM_TOTAL);

    k_prep<<<2048, 256>>>(embed_w, W_ih, W_hh, b_ih, b_hh);
    k_prep_cls<<<1, 64>>>(cls_v, cls_g);

    {   // x_proj = emb @ W_ih^T
        dim3 grid(NP / NT, MV / MT);   // (10, 79)
        k_tgemm<0><<<grid, 256, SMEM_TOTAL>>>(0, 0, nullptr, nullptr);
    }
    {   // 32 fused recurrent steps
        dim3 grid(NP / NT, BB / MT);   // (10, 32) = 320 CTAs, 2 per SM
        for (int t = 0; t < TT; t++)
            k_tgemm<1><<<grid, 256, SMEM_TOTAL>>>(t, t & 1, cap, cap_len);
    }
    k_cls<<<512, 256>>>(cls_b, out);
}

// round 11
// speedup vs baseline: 1.9573x; 1.3429x over previous
#include <cuda_runtime.h>
#include <cuda_fp16.h>
#include <math.h>
#include <stdint.h>

// ---------------- problem constants ----------------
#define BB    4096
#define TT    32
#define VOCAB 10000
#define EE    300
#define HH    300
#define KSEG  320      // padded K (single fp16 segment)
#define NP    1280     // 4H padded
#define MV    10112    // vocab padded to 128
#define NC    10       // K chunks of 32
#define MT    128
#define NT    128
#define NSTAGE 4
#define ROWB  80       // smem row stride bytes (32 cols * 2B + 16 pad)

// smem (dynamic) layout, bytes
#define SM_CAP   0          // 128 int
#define SM_LEN   512        // 128 int
#define SM_BIAS  1024       // 128 float
#define SM_STAGE 2048       // 4 stages x (A 10240 + B 10240)
#define STAGE_BYTES 20480
#define SMEM_TOTAL (SM_STAGE + NSTAGE * STAGE_BYTES)   // 83968

// ---------------- device scratch ----------------
__device__ __half g_embA[(size_t)MV * KSEG];     // emb fp16 (hi only)
__device__ __half g_wihB[(size_t)NP * KSEG];     // W_ih fp16, gate-interleaved
__device__ __half g_whhB[(size_t)NP * KSEG];     // W_hh fp16, gate-interleaved
__device__ float  g_bias[NP];
__device__ float  g_xproj[(size_t)MV * NP];
__device__ __half g_h2[2][(size_t)BB * KSEG];    // hidden fp16, double buffer
__device__ float  g_c[(size_t)BB * KSEG];
__device__ float  g_hlast[BB * HH];
__device__ float  g_wn[2 * HH];

// ---------------- PTX helpers (plain sm_80+ instructions only) ----------------
__device__ __forceinline__ uint32_t smem_u32(const void* p) {
    uint32_t a;
    asm("{ .reg .u64 t; cvta.to.shared.u64 t, %1; cvt.u32.u64 %0, t; }" : "=r"(a) : "l"(p));
    return a;
}
__device__ __forceinline__ void cp_async16(uint32_t s, const void* g) {
    asm volatile("cp.async.cg.shared.global [%0], [%1], 16;" :: "r"(s), "l"(g) : "memory");
}
__device__ __forceinline__ void cp_commit() {
    asm volatile("cp.async.commit_group;" ::: "memory");
}
__device__ __forceinline__ void cp_wait2() {
    asm volatile("cp.async.wait_group 2;" ::: "memory");
}
__device__ __forceinline__ void l2_prefetch(const void* g) {
    asm volatile("prefetch.global.L2 [%0];" :: "l"(g));
}
__device__ __forceinline__ void ldsm_x4(uint32_t* r, uint32_t addr) {
    asm volatile("ldmatrix.sync.aligned.m8n8.x4.shared.b16 {%0,%1,%2,%3}, [%4];"
                 : "=r"(r[0]), "=r"(r[1]), "=r"(r[2]), "=r"(r[3]) : "r"(addr));
}
__device__ __forceinline__ void ldsm_x2(uint32_t* r, uint32_t addr) {
    asm volatile("ldmatrix.sync.aligned.m8n8.x2.shared.b16 {%0,%1}, [%2];"
                 : "=r"(r[0]), "=r"(r[1]) : "r"(addr));
}
__device__ __forceinline__ void mma16816(float* c, const uint32_t* a, const uint32_t* b) {
    asm volatile(
        "mma.sync.aligned.m16n8k16.row.col.f32.f16.f16.f32 "
        "{%0,%1,%2,%3}, {%4,%5,%6,%7}, {%8,%9}, {%0,%1,%2,%3};"
        : "+f"(c[0]), "+f"(c[1]), "+f"(c[2]), "+f"(c[3])
        : "r"(a[0]), "r"(a[1]), "r"(a[2]), "r"(a[3]), "r"(b[0]), "r"(b[1]));
}
__device__ __forceinline__ float fsig(float x)  { return 1.f / (1.f + __expf(-x)); }
__device__ __forceinline__ float ftanh(float x) { return 1.f - 2.f / (1.f + __expf(2.f * x)); }

// ---------------- prep: fp32 -> fp16, gate interleave, zero state ----------------
__global__ void k_prep(const float* __restrict__ embed_w,
                       const float* __restrict__ W_ih,
                       const float* __restrict__ W_hh,
                       const float* __restrict__ b_ih,
                       const float* __restrict__ b_hh)
{
    const int stride = gridDim.x * blockDim.x;
    const int i0 = blockIdx.x * blockDim.x + threadIdx.x;

    for (size_t idx = i0; idx < (size_t)MV * KSEG; idx += stride) {
        int r = idx / KSEG, k = idx - (size_t)r * KSEG;
        float v = (r < VOCAB && k < EE) ? embed_w[r * EE + k] : 0.f;
        g_embA[idx] = __float2half_rn(v);
    }
    for (size_t idx = i0; idx < (size_t)NP * KSEG; idx += stride) {
        int n = idx / KSEG, k = idx - (size_t)n * KSEG;
        int gs = n & 3, u = n >> 2;
        float vi = 0.f, vh = 0.f;
        if (u < HH && k < EE) {
            int s = (gs * HH + u) * EE + k;
            vi = W_ih[s];
            vh = W_hh[s];
        }
        g_wihB[idx] = __float2half_rn(vi);
        g_whhB[idx] = __float2half_rn(vh);
    }
    for (int n = i0; n < NP; n += stride) {
        int gs = n & 3, u = n >> 2;
        g_bias[n] = (u < HH) ? (b_ih[gs * HH + u] + b_hh[gs * HH + u]) : 0.f;
    }
    for (size_t idx = i0; idx < (size_t)BB * KSEG; idx += stride) {
        g_h2[0][idx] = __float2half_rn(0.f);
        g_h2[1][idx] = __float2half_rn(0.f);
        g_c[idx] = 0.f;
    }
}

__global__ void k_prep_cls(const float* __restrict__ cls_v,
                           const float* __restrict__ cls_g)
{
    int w = threadIdx.x >> 5;
    int lane = threadIdx.x & 31;
    if (w >= 2) return;
    float s = 0.f;
    for (int k = lane; k < HH; k += 32) {
        float v = cls_v[w * HH + k];
        s += v * v;
    }
    #pragma unroll
    for (int o = 16; o; o >>= 1) s += __shfl_xor_sync(0xffffffff, s, o);
    float scale = cls_g[w] / sqrtf(s);
    for (int k = lane; k < HH; k += 32)
        g_wn[w * HH + k] = cls_v[w * HH + k] * scale;
}

// ---------------- HMMA GEMM: C[128,128] = A[128,320] x B[128,320]^T ----------------
// MODE 0: A=g_embA, B=g_wihB -> store g_xproj
// MODE 1: A=g_h2[parity], B=g_whhB -> fused LSTM epilogue
template <int MODE>
__global__ void __launch_bounds__(256, 2) k_tgemm(int t, int parity,
                                                  const int* __restrict__ cap,
                                                  const int* __restrict__ cap_len)
{
    extern __shared__ char smem[];
    const uint32_t sb = smem_u32(smem);
    const int tid = threadIdx.x;
    const int wid = tid >> 5;
    const int lane = tid & 31;
    const int wm = wid >> 2;         // 0..1 : 64-row slice
    const int wn = wid & 3;          // 0..3 : 32-col slice
    const int m0 = blockIdx.y * MT;
    const int n0 = blockIdx.x * NT;

    const __half* Ag = (MODE == 0) ? g_embA : g_h2[parity];
    const __half* Bg = (MODE == 0) ? g_wihB : g_whhB;

    if (MODE == 1) {
        if (tid < 128) {
            const int tok = cap[(m0 + tid) * TT + t];
            ((int*)(smem + SM_CAP))[tid] = tok;
            ((int*)(smem + SM_LEN))[tid] = cap_len[m0 + tid];
            // warm L2 for the epilogue gather (this CTA's 128-col slice of row tok)
            const char* pr = (const char*)(g_xproj + (size_t)tok * NP + n0);
            l2_prefetch(pr);
            l2_prefetch(pr + 128);
            l2_prefetch(pr + 256);
            l2_prefetch(pr + 384);
        } else {
            ((float*)(smem + SM_BIAS))[tid - 128] = g_bias[n0 + tid - 128];
        }
    }

    // loader: per chunk A = 128x32 fp16 (128 rows x 4 x 16B), B same; 2 units/thread.
    const int a_row = tid >> 1;
    const int a_cu  = (tid & 1) * 2;

    uint32_t stA[NSTAGE], stB[NSTAGE];
    #pragma unroll
    for (int s = 0; s < NSTAGE; s++) {
        stA[s] = sb + SM_STAGE + s * STAGE_BYTES;
        stB[s] = stA[s] + 10240;
    }

    auto issue_chunk = [&](int c) {
        if (c < NC) {
            const int stage = c & 3;
            const int koff = c * 32;
            const __half* ap = Ag + (size_t)(m0 + a_row) * KSEG + koff + a_cu * 8;
            const __half* bp = Bg + (size_t)(n0 + a_row) * KSEG + koff + a_cu * 8;
            const uint32_t sa  = stA[stage] + a_row * ROWB + a_cu * 16;
            const uint32_t sbm = stB[stage] + a_row * ROWB + a_cu * 16;
            cp_async16(sa, ap);
            cp_async16(sa + 16, ap + 8);
            cp_async16(sbm, bp);
            cp_async16(sbm + 16, bp + 8);
        }
        cp_commit();
    };

    float acc[4][4][4];
    #pragma unroll
    for (int i = 0; i < 4; i++)
        #pragma unroll
        for (int j = 0; j < 4; j++)
            #pragma unroll
            for (int e = 0; e < 4; e++) acc[i][j][e] = 0.f;

    const uint32_t a_lrow = (uint32_t)(wm * 64 + (lane & 15)) * ROWB;
    const uint32_t a_kofs = (uint32_t)((lane >> 4) * 16);
    const uint32_t b_lrow = (uint32_t)(wn * 32 + (lane & 7)) * ROWB;
    const uint32_t b_kofs = (uint32_t)(((lane >> 3) & 1) * 16);

    issue_chunk(0);
    issue_chunk(1);
    issue_chunk(2);

    for (int c = 0; c < NC; c++) {
        cp_wait2();
        __syncthreads();
        issue_chunk(c + 3);                 // into stage freed by previous iteration
        const int stage = c & 3;
        const uint32_t sA = stA[stage], sB = stB[stage];
        #pragma unroll
        for (int k16 = 0; k16 < 2; k16++) {
            uint32_t a[4][4], b[4][2];
            #pragma unroll
            for (int i = 0; i < 4; i++)
                ldsm_x4(a[i], sA + a_lrow + i * 16 * ROWB + k16 * 32 + a_kofs);
            #pragma unroll
            for (int j = 0; j < 4; j++)
                ldsm_x2(b[j], sB + b_lrow + j * 8 * ROWB + k16 * 32 + b_kofs);
            #pragma unroll
            for (int i = 0; i < 4; i++)
                #pragma unroll
                for (int j = 0; j < 4; j++)
                    mma16816(acc[i][j], a[i], b[j]);
        }
    }

    // ---------------- epilogue ----------------
    const int lr_base = wm * 64 + (lane >> 2);
    const int nl_base = wn * 32 + 2 * (lane & 3);
    const bool odd = lane & 1;

    if (MODE == 0) {
        #pragma unroll
        for (int i = 0; i < 4; i++) {
            const int r0 = m0 + lr_base + i * 16;
            #pragma unroll
            for (int j = 0; j < 4; j++) {
                const int ng = n0 + nl_base + j * 8;
                *(float2*)(g_xproj + (size_t)r0 * NP + ng) = make_float2(acc[i][j][0], acc[i][j][1]);
                *(float2*)(g_xproj + (size_t)(r0 + 8) * NP + ng) = make_float2(acc[i][j][2], acc[i][j][3]);
            }
        }
    } else {
        const int* s_cap = (const int*)(smem + SM_CAP);
        const int* s_len = (const int*)(smem + SM_LEN);
        const float* s_bias = (const float*)(smem + SM_BIAS);
        __half* hout = g_h2[parity ^ 1];

        #pragma unroll
        for (int i = 0; i < 4; i++) {
            const int lr0 = lr_base + i * 16;
            const int r0 = m0 + lr0, r1 = r0 + 8;
            const int tok0 = s_cap[lr0], tok1 = s_cap[lr0 + 8];
            const int  rme    = odd ? r1 : r0;
            const bool lastme = odd ? (t == s_len[lr0 + 8] - 1) : (t == s_len[lr0] - 1);
            #pragma unroll
            for (int j = 0; j < 4; j++) {
                const int nl = nl_base + j * 8;
                const int ng = n0 + nl;
                const float2 x0 = *(const float2*)(g_xproj + (size_t)tok0 * NP + ng);
                const float2 x1 = *(const float2*)(g_xproj + (size_t)tok1 * NP + ng);
                const float2 bi = *(const float2*)(s_bias + nl);
                float v0 = acc[i][j][0] + x0.x + bi.x;
                float v1 = acc[i][j][1] + x0.y + bi.y;
                float v2 = acc[i][j][2] + x1.x + bi.x;
                float v3 = acc[i][j][3] + x1.y + bi.y;
                // partner exchange: even lane owns (i,f), odd owns (g,o)
                float o0 = __shfl_xor_sync(0xffffffff, v0, 1);
                float o1 = __shfl_xor_sync(0xffffffff, v1, 1);
                float o2 = __shfl_xor_sync(0xffffffff, v2, 1);
                float o3 = __shfl_xor_sync(0xffffffff, v3, 1);
                float gi, gf, gg, go;
                if (!odd) { gi = v0; gf = v1; gg = o0; go = o1; }   // row0
                else      { gi = o2; gf = o3; gg = v2; go = v3; }   // row1
                const int u = (ng - (odd ? 2 : 0)) >> 2;            // hidden unit
                float I = fsig(gi), F = fsig(gf), G = ftanh(gg), O = fsig(go);
                float cn = F * g_c[(size_t)rme * KSEG + u] + I * G;
                float hn = O * ftanh(cn);
                g_c[(size_t)rme * KSEG + u] = cn;
                hout[(size_t)rme * KSEG + u] = __float2half_rn(hn);
                if (lastme && u < HH) g_hlast[rme * HH + u] = hn;
            }
        }
    }
}

// ---------------- classifier ----------------
__global__ void k_cls(const float* __restrict__ cls_b, float* __restrict__ out)
{
    int warp = (blockIdx.x * blockDim.x + threadIdx.x) >> 5;
    int lane = threadIdx.x & 31;
    if (warp >= BB) return;
    float s0 = 0.f, s1 = 0.f;
    for (int k = lane; k < HH; k += 32) {
        float hv = g_hlast[warp * HH + k];
        s0 += hv * g_wn[k];
        s1 += hv * g_wn[HH + k];
    }
    #pragma unroll
    for (int o = 16; o; o >>= 1) {
        s0 += __shfl_xor_sync(0xffffffff, s0, o);
        s1 += __shfl_xor_sync(0xffffffff, s1, o);
    }
    if (lane == 0) {
        out[warp * 2 + 0] = s0 + cls_b[0];
        out[warp * 2 + 1] = s1 + cls_b[1];
    }
}

extern "C" void kernel_launch(void* const* d_in, const int* in_sizes, int n_in,
                              void* d_out, int out_size)
{
    const int*   cap     = (const int*)d_in[0];
    const int*   cap_len = (const int*)d_in[1];
    const float* embed_w = (const float*)d_in[2];
    const float* W_ih    = (const float*)d_in[3];
    const float* W_hh    = (const float*)d_in[4];
    const float* b_ih    = (const float*)d_in[5];
    const float* b_hh    = (const float*)d_in[6];
    const float* cls_v   = (const float*)d_in[7];
    const float* cls_g   = (const float*)d_in[8];
    const float* cls_b   = (const float*)d_in[9];
    float* out = (float*)d_out;

    cudaFuncSetAttribute(k_tgemm<0>, cudaFuncAttributeMaxDynamicSharedMemorySize, SMEM_TOTAL);
    cudaFuncSetAttribute(k_tgemm<1>, cudaFuncAttributeMaxDynamicSharedMemorySize, SMEM_TOTAL);

    k_prep<<<2048, 256>>>(embed_w, W_ih, W_hh, b_ih, b_hh);
    k_prep_cls<<<1, 64>>>(cls_v, cls_g);

    {   // x_proj = emb @ W_ih^T
        dim3 grid(NP / NT, MV / MT);   // (10, 79)
        k_tgemm<0><<<grid, 256, SMEM_TOTAL>>>(0, 0, nullptr, nullptr);
    }
    {   // 32 fused recurrent steps
        dim3 grid(NP / NT, BB / MT);   // (10, 32) = 320 CTAs, 2 per SM
        for (int t = 0; t < TT; t++)
            k_tgemm<1><<<grid, 256, SMEM_TOTAL>>>(t, t & 1, cap, cap_len);
    }
    k_cls<<<512, 256>>>(cls_b, out);
}

// round 12
// speedup vs baseline: 2.2198x; 1.1341x over previous
#include <cuda_runtime.h>
#include <cuda_fp16.h>
#include <math.h>
#include <stdint.h>

// ---------------- problem constants ----------------
#define BB    4096
#define TT    32
#define VOCAB 10000
#define EE    300
#define HH    300
#define KSEG  320      // padded K (single fp16 segment)
#define NP    1280     // 4H padded
#define MV    10112    // vocab padded to 128
#define NC    10       // K chunks of 32
#define MT    128
#define NT    160
#define NSTAGE 4
#define ROWB  80       // smem row stride bytes (32 cols * 2B + 16 pad)

// smem (dynamic) layout, bytes
#define SM_CAP   0          // 128 int
#define SM_LEN   512        // 128 int
#define SM_BIAS  1024       // 160 float
#define SM_STAGE 2048       // 4 stages x (A 10240 + B 12800)
#define A_BYTES  (128 * ROWB)           // 10240
#define B_BYTES  (160 * ROWB)           // 12800
#define STAGE_BYTES (A_BYTES + B_BYTES) // 23040
#define SMEM_TOTAL (SM_STAGE + NSTAGE * STAGE_BYTES)   // 94208

// ---------------- device scratch ----------------
__device__ __half g_embA[(size_t)MV * KSEG];     // emb fp16
__device__ __half g_wihB[(size_t)NP * KSEG];     // W_ih fp16, gate-interleaved
__device__ __half g_whhB[(size_t)NP * KSEG];     // W_hh fp16, gate-interleaved
__device__ float  g_bias[NP];
__device__ float  g_xproj[(size_t)MV * NP];
__device__ __half g_h2[2][(size_t)BB * KSEG];    // hidden fp16, double buffer
__device__ float  g_c[(size_t)BB * KSEG];
__device__ float  g_hlast[BB * HH];
__device__ float  g_wn[2 * HH];

// ---------------- PTX helpers (plain sm_80+ instructions only) ----------------
__device__ __forceinline__ uint32_t smem_u32(const void* p) {
    uint32_t a;
    asm("{ .reg .u64 t; cvta.to.shared.u64 t, %1; cvt.u32.u64 %0, t; }" : "=r"(a) : "l"(p));
    return a;
}
__device__ __forceinline__ void cp_async16(uint32_t s, const void* g) {
    asm volatile("cp.async.cg.shared.global [%0], [%1], 16;" :: "r"(s), "l"(g) : "memory");
}
__device__ __forceinline__ void cp_commit() {
    asm volatile("cp.async.commit_group;" ::: "memory");
}
__device__ __forceinline__ void cp_wait2() {
    asm volatile("cp.async.wait_group 2;" ::: "memory");
}
__device__ __forceinline__ void l2_prefetch(const void* g) {
    asm volatile("prefetch.global.L2 [%0];" :: "l"(g));
}
__device__ __forceinline__ void ldsm_x4(uint32_t* r, uint32_t addr) {
    asm volatile("ldmatrix.sync.aligned.m8n8.x4.shared.b16 {%0,%1,%2,%3}, [%4];"
                 : "=r"(r[0]), "=r"(r[1]), "=r"(r[2]), "=r"(r[3]) : "r"(addr));
}
__device__ __forceinline__ void ldsm_x2(uint32_t* r, uint32_t addr) {
    asm volatile("ldmatrix.sync.aligned.m8n8.x2.shared.b16 {%0,%1}, [%2];"
                 : "=r"(r[0]), "=r"(r[1]) : "r"(addr));
}
__device__ __forceinline__ void mma16816(float* c, const uint32_t* a, const uint32_t* b) {
    asm volatile(
        "mma.sync.aligned.m16n8k16.row.col.f32.f16.f16.f32 "
        "{%0,%1,%2,%3}, {%4,%5,%6,%7}, {%8,%9}, {%0,%1,%2,%3};"
        : "+f"(c[0]), "+f"(c[1]), "+f"(c[2]), "+f"(c[3])
        : "r"(a[0]), "r"(a[1]), "r"(a[2]), "r"(a[3]), "r"(b[0]), "r"(b[1]));
}
__device__ __forceinline__ float fsig(float x)  { return 1.f / (1.f + __expf(-x)); }
__device__ __forceinline__ float ftanh(float x) { return 1.f - 2.f / (1.f + __expf(2.f * x)); }

// ---------------- prep: fp32 -> fp16, gate interleave, zero state ----------------
__global__ void k_prep(const float* __restrict__ embed_w,
                       const float* __restrict__ W_ih,
                       const float* __restrict__ W_hh,
                       const float* __restrict__ b_ih,
                       const float* __restrict__ b_hh)
{
    const int stride = gridDim.x * blockDim.x;
    const int i0 = blockIdx.x * blockDim.x + threadIdx.x;

    for (size_t idx = i0; idx < (size_t)MV * KSEG; idx += stride) {
        int r = idx / KSEG, k = idx - (size_t)r * KSEG;
        float v = (r < VOCAB && k < EE) ? embed_w[r * EE + k] : 0.f;
        g_embA[idx] = __float2half_rn(v);
    }
    for (size_t idx = i0; idx < (size_t)NP * KSEG; idx += stride) {
        int n = idx / KSEG, k = idx - (size_t)n * KSEG;
        int gs = n & 3, u = n >> 2;
        float vi = 0.f, vh = 0.f;
        if (u < HH && k < EE) {
            int s = (gs * HH + u) * EE + k;
            vi = W_ih[s];
            vh = W_hh[s];
        }
        g_wihB[idx] = __float2half_rn(vi);
        g_whhB[idx] = __float2half_rn(vh);
    }
    for (int n = i0; n < NP; n += stride) {
        int gs = n & 3, u = n >> 2;
        g_bias[n] = (u < HH) ? (b_ih[gs * HH + u] + b_hh[gs * HH + u]) : 0.f;
    }
    for (size_t idx = i0; idx < (size_t)BB * KSEG; idx += stride) {
        g_h2[0][idx] = __float2half_rn(0.f);
        g_h2[1][idx] = __float2half_rn(0.f);
        g_c[idx] = 0.f;
    }
}

__global__ void k_prep_cls(const float* __restrict__ cls_v,
                           const float* __restrict__ cls_g)
{
    int w = threadIdx.x >> 5;
    int lane = threadIdx.x & 31;
    if (w >= 2) return;
    float s = 0.f;
    for (int k = lane; k < HH; k += 32) {
        float v = cls_v[w * HH + k];
        s += v * v;
    }
    #pragma unroll
    for (int o = 16; o; o >>= 1) s += __shfl_xor_sync(0xffffffff, s, o);
    float scale = cls_g[w] / sqrtf(s);
    for (int k = lane; k < HH; k += 32)
        g_wn[w * HH + k] = cls_v[w * HH + k] * scale;
}

// ---------------- HMMA GEMM: C[128,160] = A[128,320] x B[160,320]^T ----------------
// 8 warps as 2m x 4n; warp tile 64x40 (4 m16 x 5 n8).
// MODE 0: A=g_embA, B=g_wihB -> store g_xproj
// MODE 1: A=g_h2[parity], B=g_whhB -> fused LSTM epilogue
template <int MODE>
__global__ void __launch_bounds__(256, 2) k_tgemm(int t, int parity,
                                                  const int* __restrict__ cap,
                                                  const int* __restrict__ cap_len)
{
    extern __shared__ char smem[];
    const uint32_t sb = smem_u32(smem);
    const int tid = threadIdx.x;
    const int wid = tid >> 5;
    const int lane = tid & 31;
    const int wm = wid >> 2;         // 0..1 : 64-row slice
    const int wn = wid & 3;          // 0..3 : 40-col slice
    const int m0 = blockIdx.y * MT;
    const int n0 = blockIdx.x * NT;

    const __half* Ag = (MODE == 0) ? g_embA : g_h2[parity];
    const __half* Bg = (MODE == 0) ? g_wihB : g_whhB;

    if (MODE == 1) {
        if (tid < 128) {
            const int tok = cap[(m0 + tid) * TT + t];
            ((int*)(smem + SM_CAP))[tid] = tok;
            ((int*)(smem + SM_LEN))[tid] = cap_len[m0 + tid];
            // warm L2 for the epilogue gather (this CTA's 160-col slice of row tok)
            const char* pr = (const char*)(g_xproj + (size_t)tok * NP + n0);
            l2_prefetch(pr);
            l2_prefetch(pr + 128);
            l2_prefetch(pr + 256);
            l2_prefetch(pr + 384);
            l2_prefetch(pr + 512);
        }
        if (tid >= 96) {
            ((float*)(smem + SM_BIAS))[tid - 96] = g_bias[n0 + tid - 96];
        }
    }

    uint32_t stA[NSTAGE], stB[NSTAGE];
    #pragma unroll
    for (int s = 0; s < NSTAGE; s++) {
        stA[s] = sb + SM_STAGE + s * STAGE_BYTES;
        stB[s] = stA[s] + A_BYTES;
    }

    // loader geometry (per chunk of 32 k, 16B units):
    //   A: 128 rows x 4 units = 512 -> 2 units/thread
    //   B: 160 rows x 4 units = 640 -> 2 units/thread + 1 extra for tid<128
    const int a_row = tid >> 1;
    const int a_cu  = (tid & 1) * 2;
    const int b_row = tid >> 1;           // ids 2t,2t+1 -> same row, units (t&1)*2,+1
    const int b_cu  = (tid & 1) * 2;
    const int bx_row = 128 + (tid >> 2);  // extra B rows 128..159 (tid<128)
    const int bx_cu  = tid & 3;

    auto issue_chunk = [&](int c) {
        if (c < NC) {
            const int stage = c & 3;
            const int koff = c * 32;
            const __half* ap = Ag + (size_t)(m0 + a_row) * KSEG + koff + a_cu * 8;
            const __half* bp = Bg + (size_t)(n0 + b_row) * KSEG + koff + b_cu * 8;
            const uint32_t sa  = stA[stage] + a_row * ROWB + a_cu * 16;
            const uint32_t sbm = stB[stage] + b_row * ROWB + b_cu * 16;
            cp_async16(sa, ap);
            cp_async16(sa + 16, ap + 8);
            cp_async16(sbm, bp);
            cp_async16(sbm + 16, bp + 8);
            if (tid < 128) {
                cp_async16(stB[stage] + bx_row * ROWB + bx_cu * 16,
                           Bg + (size_t)(n0 + bx_row) * KSEG + koff + bx_cu * 8);
            }
        }
        cp_commit();
    };

    float acc[4][5][4];
    #pragma unroll
    for (int i = 0; i < 4; i++)
        #pragma unroll
        for (int j = 0; j < 5; j++)
            #pragma unroll
            for (int e = 0; e < 4; e++) acc[i][j][e] = 0.f;

    const uint32_t a_lrow = (uint32_t)(wm * 64 + (lane & 15)) * ROWB;
    const uint32_t a_kofs = (uint32_t)((lane >> 4) * 16);
    // B x4 (tiles pair): rows wn*40 + pairSel*8 + (lane&7), k half by lane>>3 bit
    const uint32_t b4_lrow = (uint32_t)(wn * 40 + ((lane >> 4) & 1) * 8 + (lane & 7)) * ROWB;
    const uint32_t b4_kofs = (uint32_t)(((lane >> 3) & 1) * 16);
    // B x2 (tile 4): rows wn*40+32+(lane&7), lanes 0..15
    const uint32_t b2_lrow = (uint32_t)(wn * 40 + 32 + (lane & 7)) * ROWB;
    const uint32_t b2_kofs = (uint32_t)(((lane >> 3) & 1) * 16);

    issue_chunk(0);
    issue_chunk(1);
    issue_chunk(2);

    for (int c = 0; c < NC; c++) {
        cp_wait2();
        __syncthreads();
        issue_chunk(c + 3);                 // into stage freed by previous iteration
        const int stage = c & 3;
        const uint32_t sA = stA[stage], sB = stB[stage];
        #pragma unroll
        for (int k16 = 0; k16 < 2; k16++) {
            uint32_t a[4][4];
            #pragma unroll
            for (int i = 0; i < 4; i++)
                ldsm_x4(a[i], sA + a_lrow + i * 16 * ROWB + k16 * 32 + a_kofs);
            #pragma unroll
            for (int j2 = 0; j2 < 2; j2++) {
                uint32_t b4[4];
                ldsm_x4(b4, sB + b4_lrow + j2 * 16 * ROWB + k16 * 32 + b4_kofs);
                #pragma unroll
                for (int i = 0; i < 4; i++) {
                    mma16816(acc[i][2 * j2 + 0], a[i], &b4[0]);
                    mma16816(acc[i][2 * j2 + 1], a[i], &b4[2]);
                }
            }
            {
                uint32_t b2[2];
                ldsm_x2(b2, sB + b2_lrow + k16 * 32 + b2_kofs);
                #pragma unroll
                for (int i = 0; i < 4; i++)
                    mma16816(acc[i][4], a[i], b2);
            }
        }
    }

    // ---------------- epilogue ----------------
    const int lr_base = wm * 64 + (lane >> 2);
    const int nl_base = wn * 40 + 2 * (lane & 3);
    const bool odd = lane & 1;

    if (MODE == 0) {
        #pragma unroll
        for (int i = 0; i < 4; i++) {
            const int r0 = m0 + lr_base + i * 16;
            #pragma unroll
            for (int j = 0; j < 5; j++) {
                const int ng = n0 + nl_base + j * 8;
                *(float2*)(g_xproj + (size_t)r0 * NP + ng) = make_float2(acc[i][j][0], acc[i][j][1]);
                *(float2*)(g_xproj + (size_t)(r0 + 8) * NP + ng) = make_float2(acc[i][j][2], acc[i][j][3]);
            }
        }
    } else {
        const int* s_cap = (const int*)(smem + SM_CAP);
        const int* s_len = (const int*)(smem + SM_LEN);
        const float* s_bias = (const float*)(smem + SM_BIAS);
        __half* hout = g_h2[parity ^ 1];

        #pragma unroll
        for (int i = 0; i < 4; i++) {
            const int lr0 = lr_base + i * 16;
            const int r0 = m0 + lr0, r1 = r0 + 8;
            const int tok0 = s_cap[lr0], tok1 = s_cap[lr0 + 8];
            const int  rme    = odd ? r1 : r0;
            const bool lastme = odd ? (t == s_len[lr0 + 8] - 1) : (t == s_len[lr0] - 1);
            #pragma unroll
            for (int j = 0; j < 5; j++) {
                const int nl = nl_base + j * 8;
                const int ng = n0 + nl;
                const float2 x0 = *(const float2*)(g_xproj + (size_t)tok0 * NP + ng);
                const float2 x1 = *(const float2*)(g_xproj + (size_t)tok1 * NP + ng);
                const float2 bi = *(const float2*)(s_bias + nl);
                float v0 = acc[i][j][0] + x0.x + bi.x;
                float v1 = acc[i][j][1] + x0.y + bi.y;
                float v2 = acc[i][j][2] + x1.x + bi.x;
                float v3 = acc[i][j][3] + x1.y + bi.y;
                // partner exchange: even lane owns (i,f), odd owns (g,o)
                float o0 = __shfl_xor_sync(0xffffffff, v0, 1);
                float o1 = __shfl_xor_sync(0xffffffff, v1, 1);
                float o2 = __shfl_xor_sync(0xffffffff, v2, 1);
                float o3 = __shfl_xor_sync(0xffffffff, v3, 1);
                float gi, gf, gg, go;
                if (!odd) { gi = v0; gf = v1; gg = o0; go = o1; }   // row0
                else      { gi = o2; gf = o3; gg = v2; go = v3; }   // row1
                const int u = (ng - (odd ? 2 : 0)) >> 2;            // hidden unit
                float I = fsig(gi), F = fsig(gf), G = ftanh(gg), O = fsig(go);
                float cn = F * g_c[(size_t)rme * KSEG + u] + I * G;
                float hn = O * ftanh(cn);
                g_c[(size_t)rme * KSEG + u] = cn;
                hout[(size_t)rme * KSEG + u] = __float2half_rn(hn);
                if (lastme && u < HH) g_hlast[rme * HH + u] = hn;
            }
        }
    }
}

// ---------------- classifier ----------------
__global__ void k_cls(const float* __restrict__ cls_b, float* __restrict__ out)
{
    int warp = (blockIdx.x * blockDim.x + threadIdx.x) >> 5;
    int lane = threadIdx.x & 31;
    if (warp >= BB) return;
    float s0 = 0.f, s1 = 0.f;
    for (int k = lane; k < HH; k += 32) {
        float hv = g_hlast[warp * HH + k];
        s0 += hv * g_wn[k];
        s1 += hv * g_wn[HH + k];
    }
    #pragma unroll
    for (int o = 16; o; o >>= 1) {
        s0 += __shfl_xor_sync(0xffffffff, s0, o);
        s1 += __shfl_xor_sync(0xffffffff, s1, o);
    }
    if (lane == 0) {
        out[warp * 2 + 0] = s0 + cls_b[0];
        out[warp * 2 + 1] = s1 + cls_b[1];
    }
}

extern "C" void kernel_launch(void* const* d_in, const int* in_sizes, int n_in,
                              void* d_out, int out_size)
{
    const int*   cap     = (const int*)d_in[0];
    const int*   cap_len = (const int*)d_in[1];
    const float* embed_w = (const float*)d_in[2];
    const float* W_ih    = (const float*)d_in[3];
    const float* W_hh    = (const float*)d_in[4];
    const float* b_ih    = (const float*)d_in[5];
    const float* b_hh    = (const float*)d_in[6];
    const float* cls_v   = (const float*)d_in[7];
    const float* cls_g   = (const float*)d_in[8];
    const float* cls_b   = (const float*)d_in[9];
    float* out = (float*)d_out;

    cudaFuncSetAttribute(k_tgemm<0>, cudaFuncAttributeMaxDynamicSharedMemorySize, SMEM_TOTAL);
    cudaFuncSetAttribute(k_tgemm<1>, cudaFuncAttributeMaxDynamicSharedMemorySize, SMEM_TOTAL);

    k_prep<<<2048, 256>>>(embed_w, W_ih, W_hh, b_ih, b_hh);
    k_prep_cls<<<1, 64>>>(cls_v, cls_g);

    {   // x_proj = emb @ W_ih^T
        dim3 grid(NP / NT, MV / MT);   // (8, 79)
        k_tgemm<0><<<grid, 256, SMEM_TOTAL>>>(0, 0, nullptr, nullptr);
    }
    {   // 32 fused recurrent steps
        dim3 grid(NP / NT, BB / MT);   // (8, 32) = 256 CTAs -> one resident wave
        for (int t = 0; t < TT; t++)
            k_tgemm<1><<<grid, 256, SMEM_TOTAL>>>(t, t & 1, cap, cap_len);
    }
    k_cls<<<512, 256>>>(cls_b, out);
}

// round 15
// speedup vs baseline: 2.2640x; 1.0199x over previous
#include <cuda_runtime.h>
#include <cuda_fp16.h>
#include <math.h>
#include <stdint.h>

// ---------------- problem constants ----------------
#define BB    4096
#define TT    32
#define VOCAB 10000
#define EE    300
#define HH    300
#define KSEG  320      // padded K (single fp16 segment)
#define NP    1280     // 4H padded
#define MV    10112    // vocab padded to 128
#define NC    10       // K chunks of 32
#define ROWB  80       // smem row stride bytes (32 cols * 2B + 16 pad)

// ----- x_proj kernel tiling (R12 geometry) -----
#define XMT 128
#define XNT 160
#define XSM_STAGE 0
#define XA_BYTES  (128 * ROWB)
#define XB_BYTES  (160 * ROWB)
#define XSTAGE_BYTES (XA_BYTES + XB_BYTES)          // 23040
#define XSMEM_TOTAL (4 * XSTAGE_BYTES)              // 92160

// ----- persistent step kernel tiling -----
#define PMT 256
#define PNT 160
#define PNCTA 128            // (NP/PNT=8) x (BB/PMT=16)
// smem layout (bytes)
#define PSM_CAP   0                          // 256 int
#define PSM_LEN   1024                       // 256 int
#define PSM_BIAS  2048                       // 160 float -> 2688
#define PSM_A     2816                       // 3 stages x 20480
#define PA_BYTES  (256 * ROWB)               // 20480
#define PSM_B     (PSM_A + 3 * PA_BYTES)     // 64256
#define PB_PLANE  (160 * ROWB)               // 12800
#define PSMEM_TOTAL (PSM_B + NC * PB_PLANE)  // 192256

// ---------------- device scratch ----------------
__device__ __half g_embA[(size_t)MV * KSEG];     // emb fp16
__device__ __half g_wihB[(size_t)NP * KSEG];     // W_ih fp16, gate-interleaved
__device__ __half g_whhB[(size_t)NP * KSEG];     // W_hh fp16, gate-interleaved
__device__ float  g_bias[NP];
__device__ float  g_xproj[(size_t)MV * NP];
__device__ __half g_h2[2][(size_t)BB * KSEG];    // hidden fp16, double buffer
__device__ float  g_c[(size_t)BB * KSEG];
__device__ float  g_hlast[BB * HH];
__device__ float  g_wn[2 * HH];
__device__ unsigned int          g_bar_count = 0;
__device__ volatile unsigned int g_bar_gen   = 0;

// ---------------- PTX helpers (plain sm_80+ instructions only) ----------------
__device__ __forceinline__ uint32_t smem_u32(const void* p) {
    uint32_t a;
    asm("{ .reg .u64 t; cvta.to.shared.u64 t, %1; cvt.u32.u64 %0, t; }" : "=r"(a) : "l"(p));
    return a;
}
__device__ __forceinline__ void cp_async16(uint32_t s, const void* g) {
    asm volatile("cp.async.cg.shared.global [%0], [%1], 16;" :: "r"(s), "l"(g) : "memory");
}
__device__ __forceinline__ void cp_commit() {
    asm volatile("cp.async.commit_group;" ::: "memory");
}
__device__ __forceinline__ void cp_wait0() {
    asm volatile("cp.async.wait_group 0;" ::: "memory");
}
__device__ __forceinline__ void cp_wait1() {
    asm volatile("cp.async.wait_group 1;" ::: "memory");
}
__device__ __forceinline__ void cp_wait2() {
    asm volatile("cp.async.wait_group 2;" ::: "memory");
}
__device__ __forceinline__ void l2_prefetch(const void* g) {
    asm volatile("prefetch.global.L2 [%0];" :: "l"(g));
}
__device__ __forceinline__ void ldsm_x4(uint32_t* r, uint32_t addr) {
    asm volatile("ldmatrix.sync.aligned.m8n8.x4.shared.b16 {%0,%1,%2,%3}, [%4];"
                 : "=r"(r[0]), "=r"(r[1]), "=r"(r[2]), "=r"(r[3]) : "r"(addr));
}
__device__ __forceinline__ void ldsm_x2(uint32_t* r, uint32_t addr) {
    asm volatile("ldmatrix.sync.aligned.m8n8.x2.shared.b16 {%0,%1}, [%2];"
                 : "=r"(r[0]), "=r"(r[1]) : "r"(addr));
}
__device__ __forceinline__ void mma16816(float* c, const uint32_t* a, const uint32_t* b) {
    asm volatile(
        "mma.sync.aligned.m16n8k16.row.col.f32.f16.f16.f32 "
        "{%0,%1,%2,%3}, {%4,%5,%6,%7}, {%8,%9}, {%0,%1,%2,%3};"
        : "+f"(c[0]), "+f"(c[1]), "+f"(c[2]), "+f"(c[3])
        : "r"(a[0]), "r"(a[1]), "r"(a[2]), "r"(a[3]), "r"(b[0]), "r"(b[1]));
}
__device__ __forceinline__ float fsig(float x)  { return 1.f / (1.f + __expf(-x)); }
__device__ __forceinline__ float ftanh(float x) { return 1.f - 2.f / (1.f + __expf(2.f * x)); }

// ---------------- prep: fp32 -> fp16, gate interleave, zero state ----------------
__global__ void k_prep(const float* __restrict__ embed_w,
                       const float* __restrict__ W_ih,
                       const float* __restrict__ W_hh,
                       const float* __restrict__ b_ih,
                       const float* __restrict__ b_hh)
{
    const int stride = gridDim.x * blockDim.x;
    const int i0 = blockIdx.x * blockDim.x + threadIdx.x;
    if (i0 == 0) { g_bar_count = 0; g_bar_gen = 0; }

    for (size_t idx = i0; idx < (size_t)MV * KSEG; idx += stride) {
        int r = idx / KSEG, k = idx - (size_t)r * KSEG;
        float v = (r < VOCAB && k < EE) ? embed_w[r * EE + k] : 0.f;
        g_embA[idx] = __float2half_rn(v);
    }
    for (size_t idx = i0; idx < (size_t)NP * KSEG; idx += stride) {
        int n = idx / KSEG, k = idx - (size_t)n * KSEG;
        int gs = n & 3, u = n >> 2;
        float vi = 0.f, vh = 0.f;
        if (u < HH && k < EE) {
            int s = (gs * HH + u) * EE + k;
            vi = W_ih[s];
            vh = W_hh[s];
        }
        g_wihB[idx] = __float2half_rn(vi);
        g_whhB[idx] = __float2half_rn(vh);
    }
    for (int n = i0; n < NP; n += stride) {
        int gs = n & 3, u = n >> 2;
        g_bias[n] = (u < HH) ? (b_ih[gs * HH + u] + b_hh[gs * HH + u]) : 0.f;
    }
    for (size_t idx = i0; idx < (size_t)BB * KSEG; idx += stride) {
        g_h2[0][idx] = __float2half_rn(0.f);
        g_h2[1][idx] = __float2half_rn(0.f);
        g_c[idx] = 0.f;
    }
}

__global__ void k_prep_cls(const float* __restrict__ cls_v,
                           const float* __restrict__ cls_g)
{
    int w = threadIdx.x >> 5;
    int lane = threadIdx.x & 31;
    if (w >= 2) return;
    float s = 0.f;
    for (int k = lane; k < HH; k += 32) {
        float v = cls_v[w * HH + k];
        s += v * v;
    }
    #pragma unroll
    for (int o = 16; o; o >>= 1) s += __shfl_xor_sync(0xffffffff, s, o);
    float scale = cls_g[w] / sqrtf(s);
    for (int k = lane; k < HH; k += 32)
        g_wn[w * HH + k] = cls_v[w * HH + k] * scale;
}

// ---------------- x_proj GEMM: C[128,160] = emb[128,320] x W_ih[160,320]^T ----------------
__global__ void __launch_bounds__(256, 2) k_xproj()
{
    extern __shared__ char smem[];
    const uint32_t sb = smem_u32(smem);
    const int tid = threadIdx.x;
    const int wid = tid >> 5;
    const int lane = tid & 31;
    const int wm = wid >> 2;
    const int wn = wid & 3;
    const int m0 = blockIdx.y * XMT;
    const int n0 = blockIdx.x * XNT;

    uint32_t stA[4], stB[4];
    #pragma unroll
    for (int s = 0; s < 4; s++) {
        stA[s] = sb + XSM_STAGE + s * XSTAGE_BYTES;
        stB[s] = stA[s] + XA_BYTES;
    }

    const int a_row = tid >> 1;
    const int a_cu  = (tid & 1) * 2;
    const int bx_row = 128 + (tid >> 2);
    const int bx_cu  = tid & 3;

    auto issue_chunk = [&](int c) {
        if (c < NC) {
            const int stage = c & 3;
            const int koff = c * 32;
            const __half* ap = g_embA + (size_t)(m0 + a_row) * KSEG + koff + a_cu * 8;
            const __half* bp = g_wihB + (size_t)(n0 + a_row) * KSEG + koff + a_cu * 8;
            const uint32_t sa  = stA[stage] + a_row * ROWB + a_cu * 16;
            const uint32_t sbm = stB[stage] + a_row * ROWB + a_cu * 16;
            cp_async16(sa, ap);
            cp_async16(sa + 16, ap + 8);
            cp_async16(sbm, bp);
            cp_async16(sbm + 16, bp + 8);
            if (tid < 128)
                cp_async16(stB[stage] + bx_row * ROWB + bx_cu * 16,
                           g_wihB + (size_t)(n0 + bx_row) * KSEG + koff + bx_cu * 8);
        }
        cp_commit();
    };

    float acc[4][5][4];
    #pragma unroll
    for (int i = 0; i < 4; i++)
        #pragma unroll
        for (int j = 0; j < 5; j++)
            #pragma unroll
            for (int e = 0; e < 4; e++) acc[i][j][e] = 0.f;

    const uint32_t a_lrow = (uint32_t)(wm * 64 + (lane & 15)) * ROWB;
    const uint32_t a_kofs = (uint32_t)((lane >> 4) * 16);
    const uint32_t b4_lrow = (uint32_t)(wn * 40 + ((lane >> 4) & 1) * 8 + (lane & 7)) * ROWB;
    const uint32_t b4_kofs = (uint32_t)(((lane >> 3) & 1) * 16);
    const uint32_t b2_lrow = (uint32_t)(wn * 40 + 32 + (lane & 7)) * ROWB;
    const uint32_t b2_kofs = (uint32_t)(((lane >> 3) & 1) * 16);

    issue_chunk(0);
    issue_chunk(1);
    issue_chunk(2);

    for (int c = 0; c < NC; c++) {
        cp_wait2();
        __syncthreads();
        issue_chunk(c + 3);            // 4 stages: (c+3)&3 != c&3, no collision
        const int stage = c & 3;
        const uint32_t sA = stA[stage], sB = stB[stage];
        #pragma unroll
        for (int k16 = 0; k16 < 2; k16++) {
            uint32_t a[4][4];
            #pragma unroll
            for (int i = 0; i < 4; i++)
                ldsm_x4(a[i], sA + a_lrow + i * 16 * ROWB + k16 * 32 + a_kofs);
            #pragma unroll
            for (int j2 = 0; j2 < 2; j2++) {
                uint32_t b4[4];
                ldsm_x4(b4, sB + b4_lrow + j2 * 16 * ROWB + k16 * 32 + b4_kofs);
                #pragma unroll
                for (int i = 0; i < 4; i++) {
                    mma16816(acc[i][2 * j2 + 0], a[i], &b4[0]);
                    mma16816(acc[i][2 * j2 + 1], a[i], &b4[2]);
                }
            }
            {
                uint32_t b2[2];
                ldsm_x2(b2, sB + b2_lrow + k16 * 32 + b2_kofs);
                #pragma unroll
                for (int i = 0; i < 4; i++)
                    mma16816(acc[i][4], a[i], b2);
            }
        }
    }

    const int lr_base = wm * 64 + (lane >> 2);
    const int nl_base = wn * 40 + 2 * (lane & 3);
    #pragma unroll
    for (int i = 0; i < 4; i++) {
        const int r0 = m0 + lr_base + i * 16;
        #pragma unroll
        for (int j = 0; j < 5; j++) {
            const int ng = n0 + nl_base + j * 8;
            *(float2*)(g_xproj + (size_t)r0 * NP + ng) = make_float2(acc[i][j][0], acc[i][j][1]);
            *(float2*)(g_xproj + (size_t)(r0 + 8) * NP + ng) = make_float2(acc[i][j][2], acc[i][j][3]);
        }
    }
}

// ---------------- persistent recurrent kernel ----------------
// 128 CTAs (8n x 16m), tile 256x160, 512 threads (4m x 4n warps, warp tile 64x40).
// W_hh tile resident in smem across all 32 timesteps; device-wide barrier per step.
// A pipeline: 3 stages, issue chunk c+2 in iteration c (no stage collision).
__global__ void __launch_bounds__(512, 1) k_steps(const int* __restrict__ cap,
                                                  const int* __restrict__ cap_len)
{
    extern __shared__ char smem[];
    const uint32_t sb = smem_u32(smem);
    const int tid = threadIdx.x;
    const int wid = tid >> 5;
    const int lane = tid & 31;
    const int wm = wid >> 2;         // 0..3 : 64-row slice
    const int wn = wid & 3;          // 0..3 : 40-col slice
    const int m0 = blockIdx.y * PMT;
    const int n0 = blockIdx.x * PNT;

    int* s_cap = (int*)(smem + PSM_CAP);
    int* s_len = (int*)(smem + PSM_LEN);
    float* s_bias = (float*)(smem + PSM_BIAS);

    if (tid < 256) s_len[tid] = cap_len[m0 + tid];
    if (tid >= 256 && tid < 416) s_bias[tid - 256] = g_bias[n0 + tid - 256];

    // ---- load resident B (W_hh) tile: 10 planes of 160 rows x 32 cols ----
    const uint32_t sbB = sb + PSM_B;
    for (int u = tid; u < NC * 640; u += 512) {
        const int plane = u / 640;
        const int rem = u - plane * 640;
        const int row = rem >> 2;
        const int cu = rem & 3;
        cp_async16(sbB + plane * PB_PLANE + row * ROWB + cu * 16,
                   g_whhB + (size_t)(n0 + row) * KSEG + plane * 32 + cu * 8);
    }
    cp_commit();
    cp_wait0();
    __syncthreads();

    // A loader geometry: 256 rows x 4 units, 2 units/thread
    const int a_row = tid >> 1;
    const int a_cu  = (tid & 1) * 2;
    uint32_t stA[3];
    #pragma unroll
    for (int s = 0; s < 3; s++) stA[s] = sb + PSM_A + s * PA_BYTES;

    // ldmatrix addressing
    const uint32_t a_lrow = (uint32_t)(wm * 64 + (lane & 15)) * ROWB;
    const uint32_t a_kofs = (uint32_t)((lane >> 4) * 16);
    const uint32_t b4_lrow = (uint32_t)(wn * 40 + ((lane >> 4) & 1) * 8 + (lane & 7)) * ROWB;
    const uint32_t b4_kofs = (uint32_t)(((lane >> 3) & 1) * 16);
    const uint32_t b2_lrow = (uint32_t)(wn * 40 + 32 + (lane & 7)) * ROWB;
    const uint32_t b2_kofs = (uint32_t)(((lane >> 3) & 1) * 16);

    const int lr_base = wm * 64 + (lane >> 2);
    const int nl_base = wn * 40 + 2 * (lane & 3);
    const bool odd = lane & 1;

    unsigned int bar_gen = g_bar_gen;   // barrier generation baseline

    for (int t = 0; t < TT; t++) {
        const int parity = t & 1;
        const __half* Ag = g_h2[parity];
        __half* hout = g_h2[parity ^ 1];

        // tokens + L2 prefetch of gather rows for this step
        if (tid < 256) {
            const int tok = cap[(m0 + tid) * TT + t];
            s_cap[tid] = tok;
            const char* pr = (const char*)(g_xproj + (size_t)tok * NP + n0);
            l2_prefetch(pr);
            l2_prefetch(pr + 128);
            l2_prefetch(pr + 256);
            l2_prefetch(pr + 384);
            l2_prefetch(pr + 512);
        }
        __syncthreads();

        auto issue_chunk = [&](int c) {
            if (c < NC) {
                const int stage = c % 3;
                const int koff = c * 32;
                const __half* ap = Ag + (size_t)(m0 + a_row) * KSEG + koff + a_cu * 8;
                const uint32_t sa = stA[stage] + a_row * ROWB + a_cu * 16;
                cp_async16(sa, ap);
                cp_async16(sa + 16, ap + 8);
            }
            cp_commit();
        };

        float acc[4][5][4];
        #pragma unroll
        for (int i = 0; i < 4; i++)
            #pragma unroll
            for (int j = 0; j < 5; j++)
                #pragma unroll
                for (int e = 0; e < 4; e++) acc[i][j][e] = 0.f;

        issue_chunk(0);
        issue_chunk(1);

        for (int c = 0; c < NC; c++) {
            cp_wait1();                 // chunk c complete (only c+1 may be pending)
            __syncthreads();
            issue_chunk(c + 2);         // stage (c+2)%3: freed last iteration
            const uint32_t sA = stA[c % 3];
            const uint32_t sB = sbB + c * PB_PLANE;
            #pragma unroll
            for (int k16 = 0; k16 < 2; k16++) {
                uint32_t a[4][4];
                #pragma unroll
                for (int i = 0; i < 4; i++)
                    ldsm_x4(a[i], sA + a_lrow + i * 16 * ROWB + k16 * 32 + a_kofs);
                #pragma unroll
                for (int j2 = 0; j2 < 2; j2++) {
                    uint32_t b4[4];
                    ldsm_x4(b4, sB + b4_lrow + j2 * 16 * ROWB + k16 * 32 + b4_kofs);
                    #pragma unroll
                    for (int i = 0; i < 4; i++) {
                        mma16816(acc[i][2 * j2 + 0], a[i], &b4[0]);
                        mma16816(acc[i][2 * j2 + 1], a[i], &b4[2]);
                    }
                }
                {
                    uint32_t b2[2];
                    ldsm_x2(b2, sB + b2_lrow + k16 * 32 + b2_kofs);
                    #pragma unroll
                    for (int i = 0; i < 4; i++)
                        mma16816(acc[i][4], a[i], b2);
                }
            }
        }

        // ---- fused LSTM epilogue ----
        #pragma unroll
        for (int i = 0; i < 4; i++) {
            const int lr0 = lr_base + i * 16;
            const int r0 = m0 + lr0, r1 = r0 + 8;
            const int tok0 = s_cap[lr0], tok1 = s_cap[lr0 + 8];
            const int  rme    = odd ? r1 : r0;
            const bool lastme = odd ? (t == s_len[lr0 + 8] - 1) : (t == s_len[lr0] - 1);
            #pragma unroll
            for (int j = 0; j < 5; j++) {
                const int nl = nl_base + j * 8;
                const int ng = n0 + nl;
                const float2 x0 = *(const float2*)(g_xproj + (size_t)tok0 * NP + ng);
                const float2 x1 = *(const float2*)(g_xproj + (size_t)tok1 * NP + ng);
                const float2 bi = *(const float2*)(s_bias + nl);
                float v0 = acc[i][j][0] + x0.x + bi.x;
                float v1 = acc[i][j][1] + x0.y + bi.y;
                float v2 = acc[i][j][2] + x1.x + bi.x;
                float v3 = acc[i][j][3] + x1.y + bi.y;
                float o0 = __shfl_xor_sync(0xffffffff, v0, 1);
                float o1 = __shfl_xor_sync(0xffffffff, v1, 1);
                float o2 = __shfl_xor_sync(0xffffffff, v2, 1);
                float o3 = __shfl_xor_sync(0xffffffff, v3, 1);
                float gi, gf, gg, go;
                if (!odd) { gi = v0; gf = v1; gg = o0; go = o1; }   // row0
                else      { gi = o2; gf = o3; gg = v2; go = v3; }   // row1
                const int u = (ng - (odd ? 2 : 0)) >> 2;
                float I = fsig(gi), F = fsig(gf), G = ftanh(gg), O = fsig(go);
                float cn = F * g_c[(size_t)rme * KSEG + u] + I * G;
                float hn = O * ftanh(cn);
                g_c[(size_t)rme * KSEG + u] = cn;
                hout[(size_t)rme * KSEG + u] = __float2half_rn(hn);
                if (lastme && u < HH) g_hlast[rme * HH + u] = hn;
            }
        }

        // ---- device-wide barrier (all 128 CTAs resident) ----
        __threadfence();
        __syncthreads();
        if (tid == 0) {
            unsigned int arrived = atomicAdd(&g_bar_count, 1);
            if (arrived == PNCTA - 1) {
                atomicExch(&g_bar_count, 0);
                __threadfence();
                g_bar_gen = bar_gen + 1;
            } else {
                while (g_bar_gen == bar_gen) { }
                __threadfence();
            }
        }
        bar_gen++;
        __syncthreads();
    }
}

// ---------------- classifier ----------------
__global__ void k_cls(const float* __restrict__ cls_b, float* __restrict__ out)
{
    int warp = (blockIdx.x * blockDim.x + threadIdx.x) >> 5;
    int lane = threadIdx.x & 31;
    if (warp >= BB) return;
    float s0 = 0.f, s1 = 0.f;
    for (int k = lane; k < HH; k += 32) {
        float hv = g_hlast[warp * HH + k];
        s0 += hv * g_wn[k];
        s1 += hv * g_wn[HH + k];
    }
    #pragma unroll
    for (int o = 16; o; o >>= 1) {
        s0 += __shfl_xor_sync(0xffffffff, s0, o);
        s1 += __shfl_xor_sync(0xffffffff, s1, o);
    }
    if (lane == 0) {
        out[warp * 2 + 0] = s0 + cls_b[0];
        out[warp * 2 + 1] = s1 + cls_b[1];
    }
}

extern "C" void kernel_launch(void* const* d_in, const int* in_sizes, int n_in,
                              void* d_out, int out_size)
{
    const int*   cap     = (const int*)d_in[0];
    const int*   cap_len = (const int*)d_in[1];
    const float* embed_w = (const float*)d_in[2];
    const float* W_ih    = (const float*)d_in[3];
    const float* W_hh    = (const float*)d_in[4];
    const float* b_ih    = (const float*)d_in[5];
    const float* b_hh    = (const float*)d_in[6];
    const float* cls_v   = (const float*)d_in[7];
    const float* cls_g   = (const float*)d_in[8];
    const float* cls_b   = (const float*)d_in[9];
    float* out = (float*)d_out;

    cudaFuncSetAttribute(k_xproj, cudaFuncAttributeMaxDynamicSharedMemorySize, XSMEM_TOTAL);
    cudaFuncSetAttribute(k_steps, cudaFuncAttributeMaxDynamicSharedMemorySize, PSMEM_TOTAL);

    k_prep<<<2048, 256>>>(embed_w, W_ih, W_hh, b_ih, b_hh);
    k_prep_cls<<<1, 64>>>(cls_v, cls_g);

    {   // x_proj = emb @ W_ih^T
        dim3 grid(NP / XNT, MV / XMT);   // (8, 79)
        k_xproj<<<grid, 256, XSMEM_TOTAL>>>();
    }
    {   // all 32 recurrent steps in one persistent kernel
        dim3 grid(NP / PNT, BB / PMT);   // (8, 16) = 128 CTAs, 1/SM
        k_steps<<<grid, 512, PSMEM_TOTAL>>>(cap, cap_len);
    }
    k_cls<<<512, 256>>>(cls_b, out);
}

// round 16
// speedup vs baseline: 2.3465x; 1.0364x over previous
#include <cuda_runtime.h>
#include <cuda_fp16.h>
#include <math.h>
#include <stdint.h>

// ---------------- problem constants ----------------
#define BB    4096
#define TT    32
#define VOCAB 10000
#define EE    300
#define HH    300
#define KSEG  320      // padded K (single fp16 segment)
#define NP    1280     // 4H padded
#define MV    10112    // vocab padded to 128
#define NC    10       // K chunks of 32
#define ROWB  80       // smem row stride bytes (32 cols * 2B + 16 pad)

// ----- x_proj kernel tiling -----
#define XMT 128
#define XNT 160
#define XA_BYTES  (128 * ROWB)
#define XB_BYTES  (160 * ROWB)
#define XSTAGE_BYTES (XA_BYTES + XB_BYTES)          // 23040
#define XSMEM_TOTAL (4 * XSTAGE_BYTES)              // 92160

// ----- persistent step kernel tiling -----
#define PMT 256
#define PNT 160
#define NGRP 16              // m-groups (BB/PMT)
#define GRP_CTAS 8           // n-CTAs per m-group (NP/PNT)
// smem layout (bytes)
#define PSM_CAP   0                          // 256 int
#define PSM_LEN   1024                       // 256 int
#define PSM_A     2048                       // 3 stages x 20480
#define PA_BYTES  (256 * ROWB)               // 20480
#define PSM_B     (PSM_A + 3 * PA_BYTES)     // 63488
#define PB_PLANE  (160 * ROWB)               // 12800
#define PSMEM_TOTAL (PSM_B + NC * PB_PLANE)  // 191488

// ---------------- device scratch ----------------
__device__ __half g_embA[(size_t)MV * KSEG];     // emb fp16
__device__ __half g_wihB[(size_t)NP * KSEG];     // W_ih fp16, gate-interleaved
__device__ __half g_whhB[(size_t)NP * KSEG];     // W_hh fp16, gate-interleaved
__device__ float  g_bias[NP];
__device__ float  g_xproj[(size_t)MV * NP];      // includes bias
__device__ __half g_h2[2][(size_t)BB * KSEG];    // hidden fp16, double buffer
__device__ float  g_c[(size_t)BB * KSEG];
__device__ float  g_hlast[BB * HH];
__device__ float  g_wn[2 * HH];
// per-m-group barriers, 128B padded
__device__ unsigned int          g_gbar_cnt[NGRP * 32];
__device__ volatile unsigned int g_gbar_gen[NGRP * 32];

// ---------------- PTX helpers (plain sm_80+ instructions only) ----------------
__device__ __forceinline__ uint32_t smem_u32(const void* p) {
    uint32_t a;
    asm("{ .reg .u64 t; cvta.to.shared.u64 t, %1; cvt.u32.u64 %0, t; }" : "=r"(a) : "l"(p));
    return a;
}
__device__ __forceinline__ void cp_async16(uint32_t s, const void* g) {
    asm volatile("cp.async.cg.shared.global [%0], [%1], 16;" :: "r"(s), "l"(g) : "memory");
}
__device__ __forceinline__ void cp_commit() {
    asm volatile("cp.async.commit_group;" ::: "memory");
}
__device__ __forceinline__ void cp_wait0() {
    asm volatile("cp.async.wait_group 0;" ::: "memory");
}
__device__ __forceinline__ void cp_wait1() {
    asm volatile("cp.async.wait_group 1;" ::: "memory");
}
__device__ __forceinline__ void cp_wait2() {
    asm volatile("cp.async.wait_group 2;" ::: "memory");
}
__device__ __forceinline__ void l2_prefetch(const void* g) {
    asm volatile("prefetch.global.L2 [%0];" :: "l"(g));
}
__device__ __forceinline__ void ldsm_x4(uint32_t* r, uint32_t addr) {
    asm volatile("ldmatrix.sync.aligned.m8n8.x4.shared.b16 {%0,%1,%2,%3}, [%4];"
                 : "=r"(r[0]), "=r"(r[1]), "=r"(r[2]), "=r"(r[3]) : "r"(addr));
}
__device__ __forceinline__ void ldsm_x2(uint32_t* r, uint32_t addr) {
    asm volatile("ldmatrix.sync.aligned.m8n8.x2.shared.b16 {%0,%1}, [%2];"
                 : "=r"(r[0]), "=r"(r[1]) : "r"(addr));
}
__device__ __forceinline__ void mma16816(float* c, const uint32_t* a, const uint32_t* b) {
    asm volatile(
        "mma.sync.aligned.m16n8k16.row.col.f32.f16.f16.f32 "
        "{%0,%1,%2,%3}, {%4,%5,%6,%7}, {%8,%9}, {%0,%1,%2,%3};"
        : "+f"(c[0]), "+f"(c[1]), "+f"(c[2]), "+f"(c[3])
        : "r"(a[0]), "r"(a[1]), "r"(a[2]), "r"(a[3]), "r"(b[0]), "r"(b[1]));
}
__device__ __forceinline__ float fsig(float x)  { return 1.f / (1.f + __expf(-x)); }
__device__ __forceinline__ float ftanh(float x) { return 1.f - 2.f / (1.f + __expf(2.f * x)); }

// ---------------- prep: fp32 -> fp16, gate interleave, zero state ----------------
__global__ void k_prep(const float* __restrict__ embed_w,
                       const float* __restrict__ W_ih,
                       const float* __restrict__ W_hh,
                       const float* __restrict__ b_ih,
                       const float* __restrict__ b_hh)
{
    const int stride = gridDim.x * blockDim.x;
    const int i0 = blockIdx.x * blockDim.x + threadIdx.x;
    if (i0 < NGRP * 32) { g_gbar_cnt[i0] = 0; g_gbar_gen[i0] = 0; }

    for (size_t idx = i0; idx < (size_t)MV * KSEG; idx += stride) {
        int r = idx / KSEG, k = idx - (size_t)r * KSEG;
        float v = (r < VOCAB && k < EE) ? embed_w[r * EE + k] : 0.f;
        g_embA[idx] = __float2half_rn(v);
    }
    for (size_t idx = i0; idx < (size_t)NP * KSEG; idx += stride) {
        int n = idx / KSEG, k = idx - (size_t)n * KSEG;
        int gs = n & 3, u = n >> 2;
        float vi = 0.f, vh = 0.f;
        if (u < HH && k < EE) {
            int s = (gs * HH + u) * EE + k;
            vi = W_ih[s];
            vh = W_hh[s];
        }
        g_wihB[idx] = __float2half_rn(vi);
        g_whhB[idx] = __float2half_rn(vh);
    }
    for (int n = i0; n < NP; n += stride) {
        int gs = n & 3, u = n >> 2;
        g_bias[n] = (u < HH) ? (b_ih[gs * HH + u] + b_hh[gs * HH + u]) : 0.f;
    }
    for (size_t idx = i0; idx < (size_t)BB * KSEG; idx += stride) {
        g_h2[0][idx] = __float2half_rn(0.f);
        g_h2[1][idx] = __float2half_rn(0.f);
        g_c[idx] = 0.f;
    }
}

__global__ void k_prep_cls(const float* __restrict__ cls_v,
                           const float* __restrict__ cls_g)
{
    int w = threadIdx.x >> 5;
    int lane = threadIdx.x & 31;
    if (w >= 2) return;
    float s = 0.f;
    for (int k = lane; k < HH; k += 32) {
        float v = cls_v[w * HH + k];
        s += v * v;
    }
    #pragma unroll
    for (int o = 16; o; o >>= 1) s += __shfl_xor_sync(0xffffffff, s, o);
    float scale = cls_g[w] / sqrtf(s);
    for (int k = lane; k < HH; k += 32)
        g_wn[w * HH + k] = cls_v[w * HH + k] * scale;
}

// ---------------- x_proj GEMM: C[128,160] = emb[128,320] x W_ih[160,320]^T  (+bias) ----------------
__global__ void __launch_bounds__(256, 2) k_xproj()
{
    extern __shared__ char smem[];
    const uint32_t sb = smem_u32(smem);
    const int tid = threadIdx.x;
    const int wid = tid >> 5;
    const int lane = tid & 31;
    const int wm = wid >> 2;
    const int wn = wid & 3;
    const int m0 = blockIdx.y * XMT;
    const int n0 = blockIdx.x * XNT;

    uint32_t stA[4], stB[4];
    #pragma unroll
    for (int s = 0; s < 4; s++) {
        stA[s] = sb + s * XSTAGE_BYTES;
        stB[s] = stA[s] + XA_BYTES;
    }

    const int a_row = tid >> 1;
    const int a_cu  = (tid & 1) * 2;
    const int bx_row = 128 + (tid >> 2);
    const int bx_cu  = tid & 3;

    auto issue_chunk = [&](int c) {
        if (c < NC) {
            const int stage = c & 3;
            const int koff = c * 32;
            const __half* ap = g_embA + (size_t)(m0 + a_row) * KSEG + koff + a_cu * 8;
            const __half* bp = g_wihB + (size_t)(n0 + a_row) * KSEG + koff + a_cu * 8;
            const uint32_t sa  = stA[stage] + a_row * ROWB + a_cu * 16;
            const uint32_t sbm = stB[stage] + a_row * ROWB + a_cu * 16;
            cp_async16(sa, ap);
            cp_async16(sa + 16, ap + 8);
            cp_async16(sbm, bp);
            cp_async16(sbm + 16, bp + 8);
            if (tid < 128)
                cp_async16(stB[stage] + bx_row * ROWB + bx_cu * 16,
                           g_wihB + (size_t)(n0 + bx_row) * KSEG + koff + bx_cu * 8);
        }
        cp_commit();
    };

    float acc[4][5][4];
    #pragma unroll
    for (int i = 0; i < 4; i++)
        #pragma unroll
        for (int j = 0; j < 5; j++)
            #pragma unroll
            for (int e = 0; e < 4; e++) acc[i][j][e] = 0.f;

    const uint32_t a_lrow = (uint32_t)(wm * 64 + (lane & 15)) * ROWB;
    const uint32_t a_kofs = (uint32_t)((lane >> 4) * 16);
    const uint32_t b4_lrow = (uint32_t)(wn * 40 + ((lane >> 4) & 1) * 8 + (lane & 7)) * ROWB;
    const uint32_t b4_kofs = (uint32_t)(((lane >> 3) & 1) * 16);
    const uint32_t b2_lrow = (uint32_t)(wn * 40 + 32 + (lane & 7)) * ROWB;
    const uint32_t b2_kofs = (uint32_t)(((lane >> 3) & 1) * 16);

    issue_chunk(0);
    issue_chunk(1);
    issue_chunk(2);

    for (int c = 0; c < NC; c++) {
        cp_wait2();
        __syncthreads();
        issue_chunk(c + 3);            // 4 stages: (c+3)&3 != c&3, no collision
        const int stage = c & 3;
        const uint32_t sA = stA[stage], sB = stB[stage];
        #pragma unroll
        for (int k16 = 0; k16 < 2; k16++) {
            uint32_t a[4][4];
            #pragma unroll
            for (int i = 0; i < 4; i++)
                ldsm_x4(a[i], sA + a_lrow + i * 16 * ROWB + k16 * 32 + a_kofs);
            #pragma unroll
            for (int j2 = 0; j2 < 2; j2++) {
                uint32_t b4[4];
                ldsm_x4(b4, sB + b4_lrow + j2 * 16 * ROWB + k16 * 32 + b4_kofs);
                #pragma unroll
                for (int i = 0; i < 4; i++) {
                    mma16816(acc[i][2 * j2 + 0], a[i], &b4[0]);
                    mma16816(acc[i][2 * j2 + 1], a[i], &b4[2]);
                }
            }
            {
                uint32_t b2[2];
                ldsm_x2(b2, sB + b2_lrow + k16 * 32 + b2_kofs);
                #pragma unroll
                for (int i = 0; i < 4; i++)
                    mma16816(acc[i][4], a[i], b2);
            }
        }
    }

    const int lr_base = wm * 64 + (lane >> 2);
    const int nl_base = wn * 40 + 2 * (lane & 3);
    #pragma unroll
    for (int i = 0; i < 4; i++) {
        const int r0 = m0 + lr_base + i * 16;
        #pragma unroll
        for (int j = 0; j < 5; j++) {
            const int ng = n0 + nl_base + j * 8;
            const float2 bi = *(const float2*)(g_bias + ng);   // fold bias here
            *(float2*)(g_xproj + (size_t)r0 * NP + ng) =
                make_float2(acc[i][j][0] + bi.x, acc[i][j][1] + bi.y);
            *(float2*)(g_xproj + (size_t)(r0 + 8) * NP + ng) =
                make_float2(acc[i][j][2] + bi.x, acc[i][j][3] + bi.y);
        }
    }
}

// ---------------- persistent recurrent kernel ----------------
// 128 CTAs (8n x 16m), tile 256x160, 512 threads (4m x 4n warps, warp tile 64x40).
// W_hh tile resident in smem across all 32 timesteps.
// Synchronization: per-m-group barrier over the 8 n-CTAs sharing rows
// [m0, m0+256) — the only real cross-CTA dependency (h rows). m-groups
// proceed independently, removing global straggler coupling.
__global__ void __launch_bounds__(512, 1) k_steps(const int* __restrict__ cap,
                                                  const int* __restrict__ cap_len)
{
    extern __shared__ char smem[];
    const uint32_t sb = smem_u32(smem);
    const int tid = threadIdx.x;
    const int wid = tid >> 5;
    const int lane = tid & 31;
    const int wm = wid >> 2;         // 0..3 : 64-row slice
    const int wn = wid & 3;          // 0..3 : 40-col slice
    const int m0 = blockIdx.y * PMT;
    const int n0 = blockIdx.x * PNT;
    const int grp = blockIdx.y;      // m-group id

    int* s_cap = (int*)(smem + PSM_CAP);
    int* s_len = (int*)(smem + PSM_LEN);

    if (tid < 256) s_len[tid] = cap_len[m0 + tid];

    // ---- load resident B (W_hh) tile: 10 planes of 160 rows x 32 cols ----
    const uint32_t sbB = sb + PSM_B;
    for (int u = tid; u < NC * 640; u += 512) {
        const int plane = u / 640;
        const int rem = u - plane * 640;
        const int row = rem >> 2;
        const int cu = rem & 3;
        cp_async16(sbB + plane * PB_PLANE + row * ROWB + cu * 16,
                   g_whhB + (size_t)(n0 + row) * KSEG + plane * 32 + cu * 8);
    }
    cp_commit();
    cp_wait0();
    __syncthreads();

    // A loader geometry: 256 rows x 4 units, 2 units/thread
    const int a_row = tid >> 1;
    const int a_cu  = (tid & 1) * 2;
    uint32_t stA[3];
    #pragma unroll
    for (int s = 0; s < 3; s++) stA[s] = sb + PSM_A + s * PA_BYTES;

    // ldmatrix addressing
    const uint32_t a_lrow = (uint32_t)(wm * 64 + (lane & 15)) * ROWB;
    const uint32_t a_kofs = (uint32_t)((lane >> 4) * 16);
    const uint32_t b4_lrow = (uint32_t)(wn * 40 + ((lane >> 4) & 1) * 8 + (lane & 7)) * ROWB;
    const uint32_t b4_kofs = (uint32_t)(((lane >> 3) & 1) * 16);
    const uint32_t b2_lrow = (uint32_t)(wn * 40 + 32 + (lane & 7)) * ROWB;
    const uint32_t b2_kofs = (uint32_t)(((lane >> 3) & 1) * 16);

    const int lr_base = wm * 64 + (lane >> 2);
    const int nl_base = wn * 40 + 2 * (lane & 3);
    const bool odd = lane & 1;

    unsigned int bar_gen = 0;

    for (int t = 0; t < TT; t++) {
        const int parity = t & 1;
        const __half* Ag = g_h2[parity];
        __half* hout = g_h2[parity ^ 1];

        // tokens + L2 prefetch of gather rows for this step
        if (tid < 256) {
            const int tok = cap[(m0 + tid) * TT + t];
            s_cap[tid] = tok;
            const char* pr = (const char*)(g_xproj + (size_t)tok * NP + n0);
            l2_prefetch(pr);
            l2_prefetch(pr + 128);
            l2_prefetch(pr + 256);
            l2_prefetch(pr + 384);
            l2_prefetch(pr + 512);
        }
        __syncthreads();

        auto issue_chunk = [&](int c) {
            if (c < NC) {
                const int stage = c % 3;
                const int koff = c * 32;
                const __half* ap = Ag + (size_t)(m0 + a_row) * KSEG + koff + a_cu * 8;
                const uint32_t sa = stA[stage] + a_row * ROWB + a_cu * 16;
                cp_async16(sa, ap);
                cp_async16(sa + 16, ap + 8);
            }
            cp_commit();
        };

        float acc[4][5][4];
        #pragma unroll
        for (int i = 0; i < 4; i++)
            #pragma unroll
            for (int j = 0; j < 5; j++)
                #pragma unroll
                for (int e = 0; e < 4; e++) acc[i][j][e] = 0.f;

        issue_chunk(0);
        issue_chunk(1);

        for (int c = 0; c < NC; c++) {
            cp_wait1();                 // chunk c complete (only c+1 may be pending)
            __syncthreads();
            issue_chunk(c + 2);         // stage (c+2)%3: freed last iteration
            const uint32_t sA = stA[c % 3];
            const uint32_t sB = sbB + c * PB_PLANE;
            #pragma unroll
            for (int k16 = 0; k16 < 2; k16++) {
                uint32_t a[4][4];
                #pragma unroll
                for (int i = 0; i < 4; i++)
                    ldsm_x4(a[i], sA + a_lrow + i * 16 * ROWB + k16 * 32 + a_kofs);
                #pragma unroll
                for (int j2 = 0; j2 < 2; j2++) {
                    uint32_t b4[4];
                    ldsm_x4(b4, sB + b4_lrow + j2 * 16 * ROWB + k16 * 32 + b4_kofs);
                    #pragma unroll
                    for (int i = 0; i < 4; i++) {
                        mma16816(acc[i][2 * j2 + 0], a[i], &b4[0]);
                        mma16816(acc[i][2 * j2 + 1], a[i], &b4[2]);
                    }
                }
                {
                    uint32_t b2[2];
                    ldsm_x2(b2, sB + b2_lrow + k16 * 32 + b2_kofs);
                    #pragma unroll
                    for (int i = 0; i < 4; i++)
                        mma16816(acc[i][4], a[i], b2);
                }
            }
        }

        // ---- fused LSTM epilogue (bias already folded into g_xproj) ----
        #pragma unroll
        for (int i = 0; i < 4; i++) {
            const int lr0 = lr_base + i * 16;
            const int r0 = m0 + lr0, r1 = r0 + 8;
            const int tok0 = s_cap[lr0], tok1 = s_cap[lr0 + 8];
            const int  rme    = odd ? r1 : r0;
            const bool lastme = odd ? (t == s_len[lr0 + 8] - 1) : (t == s_len[lr0] - 1);
            #pragma unroll
            for (int j = 0; j < 5; j++) {
                const int nl = nl_base + j * 8;
                const int ng = n0 + nl;
                const float2 x0 = *(const float2*)(g_xproj + (size_t)tok0 * NP + ng);
                const float2 x1 = *(const float2*)(g_xproj + (size_t)tok1 * NP + ng);
                float v0 = acc[i][j][0] + x0.x;
                float v1 = acc[i][j][1] + x0.y;
                float v2 = acc[i][j][2] + x1.x;
                float v3 = acc[i][j][3] + x1.y;
                float o0 = __shfl_xor_sync(0xffffffff, v0, 1);
                float o1 = __shfl_xor_sync(0xffffffff, v1, 1);
                float o2 = __shfl_xor_sync(0xffffffff, v2, 1);
                float o3 = __shfl_xor_sync(0xffffffff, v3, 1);
                float gi, gf, gg, go;
                if (!odd) { gi = v0; gf = v1; gg = o0; go = o1; }   // row0
                else      { gi = o2; gf = o3; gg = v2; go = v3; }   // row1
                const int u = (ng - (odd ? 2 : 0)) >> 2;
                float I = fsig(gi), F = fsig(gf), G = ftanh(gg), O = fsig(go);
                float cn = F * g_c[(size_t)rme * KSEG + u] + I * G;
                float hn = O * ftanh(cn);
                g_c[(size_t)rme * KSEG + u] = cn;
                hout[(size_t)rme * KSEG + u] = __float2half_rn(hn);
                if (lastme && u < HH) g_hlast[rme * HH + u] = hn;
            }
        }

        // ---- per-m-group barrier (8 CTAs sharing this m-block) ----
        __threadfence();
        __syncthreads();
        if (tid == 0) {
            unsigned int arrived = atomicAdd(&g_gbar_cnt[grp * 32], 1);
            if (arrived == GRP_CTAS - 1) {
                atomicExch(&g_gbar_cnt[grp * 32], 0);
                __threadfence();
                g_gbar_gen[grp * 32] = bar_gen + 1;
            } else {
                while (g_gbar_gen[grp * 32] == bar_gen) { }
                __threadfence();
            }
        }
        bar_gen++;
        __syncthreads();
    }
}

// ---------------- classifier ----------------
__global__ void k_cls(const float* __restrict__ cls_b, float* __restrict__ out)
{
    int warp = (blockIdx.x * blockDim.x + threadIdx.x) >> 5;
    int lane = threadIdx.x & 31;
    if (warp >= BB) return;
    float s0 = 0.f, s1 = 0.f;
    for (int k = lane; k < HH; k += 32) {
        float hv = g_hlast[warp * HH + k];
        s0 += hv * g_wn[k];
        s1 += hv * g_wn[HH + k];
    }
    #pragma unroll
    for (int o = 16; o; o >>= 1) {
        s0 += __shfl_xor_sync(0xffffffff, s0, o);
        s1 += __shfl_xor_sync(0xffffffff, s1, o);
    }
    if (lane == 0) {
        out[warp * 2 + 0] = s0 + cls_b[0];
        out[warp * 2 + 1] = s1 + cls_b[1];
    }
}

extern "C" void kernel_launch(void* const* d_in, const int* in_sizes, int n_in,
                              void* d_out, int out_size)
{
    const int*   cap     = (const int*)d_in[0];
    const int*   cap_len = (const int*)d_in[1];
    const float* embed_w = (const float*)d_in[2];
    const float* W_ih    = (const float*)d_in[3];
    const float* W_hh    = (const float*)d_in[4];
    const float* b_ih    = (const float*)d_in[5];
    const float* b_hh    = (const float*)d_in[6];
    const float* cls_v   = (const float*)d_in[7];
    const float* cls_g   = (const float*)d_in[8];
    const float* cls_b   = (const float*)d_in[9];
    float* out = (float*)d_out;

    cudaFuncSetAttribute(k_xproj, cudaFuncAttributeMaxDynamicSharedMemorySize, XSMEM_TOTAL);
    cudaFuncSetAttribute(k_steps, cudaFuncAttributeMaxDynamicSharedMemorySize, PSMEM_TOTAL);

    k_prep<<<2048, 256>>>(embed_w, W_ih, W_hh, b_ih, b_hh);
    k_prep_cls<<<1, 64>>>(cls_v, cls_g);

    {   // x_proj = emb @ W_ih^T (+bias)
        dim3 grid(NP / XNT, MV / XMT);   // (8, 79)
        k_xproj<<<grid, 256, XSMEM_TOTAL>>>();
    }
    {   // all 32 recurrent steps in one persistent kernel
        dim3 grid(NP / PNT, BB / PMT);   // (8, 16) = 128 CTAs, 1/SM
        k_steps<<<grid, 512, PSMEM_TOTAL>>>(cap, cap_len);
    }
    k_cls<<<512, 256>>>(cls_b, out);
}

// round 17
// speedup vs baseline: 4.1567x; 1.7714x over previous
#include <cuda_runtime.h>
#include <cuda_fp16.h>
#include <math.h>
#include <stdint.h>

// ---------------- problem constants ----------------
#define BB    4096
#define TT    32
#define VOCAB 10000
#define EE    300
#define HH    300
#define KSEG  320      // padded K (single fp16 segment)
#define NP    1280     // 4H padded
#define MV    10112    // vocab padded to 128
#define NC    10       // K chunks of 32
#define ROWB  80       // smem row stride bytes (32 cols * 2B + 16 pad)

// ----- x_proj kernel tiling -----
#define XMT 128
#define XNT 160
#define XA_BYTES  (128 * ROWB)
#define XB_BYTES  (160 * ROWB)
#define XSTAGE_BYTES (XA_BYTES + XB_BYTES)          // 23040
#define XSMEM_TOTAL (4 * XSTAGE_BYTES)              // 92160

// ----- persistent step kernel tiling -----
#define PMT 256
#define PNT 160
#define NGRP 16              // m-groups (BB/PMT)
#define GRP_CTAS 8           // n-CTAs per m-group (NP/PNT)
// smem layout (bytes)
#define PSM_CAP   0                          // 256 int
#define PSM_LEN   1024                       // 256 int
#define PSM_A     2048                       // 2 stages x 20480
#define PA_BYTES  (256 * ROWB)               // 20480
#define PSM_B     (PSM_A + 2 * PA_BYTES)     // 43008
#define PB_PLANE  (160 * ROWB)               // 12800
#define PSM_C     (PSM_B + NC * PB_PLANE)    // 171008
#define CSTRIDE   41                         // floats per row (pad for banks)
#define PSMEM_TOTAL (PSM_C + 256 * CSTRIDE * 4)  // 212992

// ---------------- device scratch ----------------
__device__ __half g_embA[(size_t)MV * KSEG];     // emb fp16
__device__ __half g_wihB[(size_t)NP * KSEG];     // W_ih fp16, gate-interleaved
__device__ __half g_whhB[(size_t)NP * KSEG];     // W_hh fp16, gate-interleaved
__device__ float  g_bias[NP];
__device__ __half g_xproj[(size_t)MV * NP];      // fp16, bias folded in
__device__ __half g_h2[2][(size_t)BB * KSEG];    // hidden fp16, double buffer
__device__ float  g_hlast[BB * HH];
__device__ float  g_wn[2 * HH];
// per-m-group barriers, 128B padded
__device__ unsigned int          g_gbar_cnt[NGRP * 32];
__device__ volatile unsigned int g_gbar_gen[NGRP * 32];

// ---------------- PTX helpers (plain sm_80+ instructions only) ----------------
__device__ __forceinline__ uint32_t smem_u32(const void* p) {
    uint32_t a;
    asm("{ .reg .u64 t; cvta.to.shared.u64 t, %1; cvt.u32.u64 %0, t; }" : "=r"(a) : "l"(p));
    return a;
}
__device__ __forceinline__ void cp_async16(uint32_t s, const void* g) {
    asm volatile("cp.async.cg.shared.global [%0], [%1], 16;" :: "r"(s), "l"(g) : "memory");
}
__device__ __forceinline__ void cp_commit() {
    asm volatile("cp.async.commit_group;" ::: "memory");
}
__device__ __forceinline__ void cp_wait0() {
    asm volatile("cp.async.wait_group 0;" ::: "memory");
}
__device__ __forceinline__ void cp_wait2() {
    asm volatile("cp.async.wait_group 2;" ::: "memory");
}
__device__ __forceinline__ void l2_prefetch(const void* g) {
    asm volatile("prefetch.global.L2 [%0];" :: "l"(g));
}
__device__ __forceinline__ void ldsm_x4(uint32_t* r, uint32_t addr) {
    asm volatile("ldmatrix.sync.aligned.m8n8.x4.shared.b16 {%0,%1,%2,%3}, [%4];"
                 : "=r"(r[0]), "=r"(r[1]), "=r"(r[2]), "=r"(r[3]) : "r"(addr));
}
__device__ __forceinline__ void ldsm_x2(uint32_t* r, uint32_t addr) {
    asm volatile("ldmatrix.sync.aligned.m8n8.x2.shared.b16 {%0,%1}, [%2];"
                 : "=r"(r[0]), "=r"(r[1]) : "r"(addr));
}
__device__ __forceinline__ void mma16816(float* c, const uint32_t* a, const uint32_t* b) {
    asm volatile(
        "mma.sync.aligned.m16n8k16.row.col.f32.f16.f16.f32 "
        "{%0,%1,%2,%3}, {%4,%5,%6,%7}, {%8,%9}, {%0,%1,%2,%3};"
        : "+f"(c[0]), "+f"(c[1]), "+f"(c[2]), "+f"(c[3])
        : "r"(a[0]), "r"(a[1]), "r"(a[2]), "r"(a[3]), "r"(b[0]), "r"(b[1]));
}
__device__ __forceinline__ float fsig(float x)  { return 1.f / (1.f + __expf(-x)); }
__device__ __forceinline__ float ftanh(float x) { return 1.f - 2.f / (1.f + __expf(2.f * x)); }

// ---------------- prep: fp32 -> fp16, gate interleave, zero state ----------------
__global__ void k_prep(const float* __restrict__ embed_w,
                       const float* __restrict__ W_ih,
                       const float* __restrict__ W_hh,
                       const float* __restrict__ b_ih,
                       const float* __restrict__ b_hh)
{
    const int stride = gridDim.x * blockDim.x;
    const int i0 = blockIdx.x * blockDim.x + threadIdx.x;
    if (i0 < NGRP * 32) { g_gbar_cnt[i0] = 0; g_gbar_gen[i0] = 0; }

    for (size_t idx = i0; idx < (size_t)MV * KSEG; idx += stride) {
        int r = idx / KSEG, k = idx - (size_t)r * KSEG;
        float v = (r < VOCAB && k < EE) ? embed_w[r * EE + k] : 0.f;
        g_embA[idx] = __float2half_rn(v);
    }
    for (size_t idx = i0; idx < (size_t)NP * KSEG; idx += stride) {
        int n = idx / KSEG, k = idx - (size_t)n * KSEG;
        int gs = n & 3, u = n >> 2;
        float vi = 0.f, vh = 0.f;
        if (u < HH && k < EE) {
            int s = (gs * HH + u) * EE + k;
            vi = W_ih[s];
            vh = W_hh[s];
        }
        g_wihB[idx] = __float2half_rn(vi);
        g_whhB[idx] = __float2half_rn(vh);
    }
    for (int n = i0; n < NP; n += stride) {
        int gs = n & 3, u = n >> 2;
        g_bias[n] = (u < HH) ? (b_ih[gs * HH + u] + b_hh[gs * HH + u]) : 0.f;
    }
    for (size_t idx = i0; idx < (size_t)BB * KSEG; idx += stride) {
        g_h2[0][idx] = __float2half_rn(0.f);
        g_h2[1][idx] = __float2half_rn(0.f);
    }
}

__global__ void k_prep_cls(const float* __restrict__ cls_v,
                           const float* __restrict__ cls_g)
{
    int w = threadIdx.x >> 5;
    int lane = threadIdx.x & 31;
    if (w >= 2) return;
    float s = 0.f;
    for (int k = lane; k < HH; k += 32) {
        float v = cls_v[w * HH + k];
        s += v * v;
    }
    #pragma unroll
    for (int o = 16; o; o >>= 1) s += __shfl_xor_sync(0xffffffff, s, o);
    float scale = cls_g[w] / sqrtf(s);
    for (int k = lane; k < HH; k += 32)
        g_wn[w * HH + k] = cls_v[w * HH + k] * scale;
}

// ---------------- x_proj GEMM: fp16 out, bias folded ----------------
__global__ void __launch_bounds__(256, 2) k_xproj()
{
    extern __shared__ char smem[];
    const uint32_t sb = smem_u32(smem);
    const int tid = threadIdx.x;
    const int wid = tid >> 5;
    const int lane = tid & 31;
    const int wm = wid >> 2;
    const int wn = wid & 3;
    const int m0 = blockIdx.y * XMT;
    const int n0 = blockIdx.x * XNT;

    uint32_t stA[4], stB[4];
    #pragma unroll
    for (int s = 0; s < 4; s++) {
        stA[s] = sb + s * XSTAGE_BYTES;
        stB[s] = stA[s] + XA_BYTES;
    }

    const int a_row = tid >> 1;
    const int a_cu  = (tid & 1) * 2;
    const int bx_row = 128 + (tid >> 2);
    const int bx_cu  = tid & 3;

    auto issue_chunk = [&](int c) {
        if (c < NC) {
            const int stage = c & 3;
            const int koff = c * 32;
            const __half* ap = g_embA + (size_t)(m0 + a_row) * KSEG + koff + a_cu * 8;
            const __half* bp = g_wihB + (size_t)(n0 + a_row) * KSEG + koff + a_cu * 8;
            const uint32_t sa  = stA[stage] + a_row * ROWB + a_cu * 16;
            const uint32_t sbm = stB[stage] + a_row * ROWB + a_cu * 16;
            cp_async16(sa, ap);
            cp_async16(sa + 16, ap + 8);
            cp_async16(sbm, bp);
            cp_async16(sbm + 16, bp + 8);
            if (tid < 128)
                cp_async16(stB[stage] + bx_row * ROWB + bx_cu * 16,
                           g_wihB + (size_t)(n0 + bx_row) * KSEG + koff + bx_cu * 8);
        }
        cp_commit();
    };

    float acc[4][5][4];
    #pragma unroll
    for (int i = 0; i < 4; i++)
        #pragma unroll
        for (int j = 0; j < 5; j++)
            #pragma unroll
            for (int e = 0; e < 4; e++) acc[i][j][e] = 0.f;

    const uint32_t a_lrow = (uint32_t)(wm * 64 + (lane & 15)) * ROWB;
    const uint32_t a_kofs = (uint32_t)((lane >> 4) * 16);
    const uint32_t b4_lrow = (uint32_t)(wn * 40 + ((lane >> 4) & 1) * 8 + (lane & 7)) * ROWB;
    const uint32_t b4_kofs = (uint32_t)(((lane >> 3) & 1) * 16);
    const uint32_t b2_lrow = (uint32_t)(wn * 40 + 32 + (lane & 7)) * ROWB;
    const uint32_t b2_kofs = (uint32_t)(((lane >> 3) & 1) * 16);

    issue_chunk(0);
    issue_chunk(1);
    issue_chunk(2);

    for (int c = 0; c < NC; c++) {
        cp_wait2();
        __syncthreads();
        issue_chunk(c + 3);            // 4 stages: (c+3)&3 != c&3, no collision
        const int stage = c & 3;
        const uint32_t sA = stA[stage], sB = stB[stage];
        #pragma unroll
        for (int k16 = 0; k16 < 2; k16++) {
            uint32_t a[4][4];
            #pragma unroll
            for (int i = 0; i < 4; i++)
                ldsm_x4(a[i], sA + a_lrow + i * 16 * ROWB + k16 * 32 + a_kofs);
            #pragma unroll
            for (int j2 = 0; j2 < 2; j2++) {
                uint32_t b4[4];
                ldsm_x4(b4, sB + b4_lrow + j2 * 16 * ROWB + k16 * 32 + b4_kofs);
                #pragma unroll
                for (int i = 0; i < 4; i++) {
                    mma16816(acc[i][2 * j2 + 0], a[i], &b4[0]);
                    mma16816(acc[i][2 * j2 + 1], a[i], &b4[2]);
                }
            }
            {
                uint32_t b2[2];
                ldsm_x2(b2, sB + b2_lrow + k16 * 32 + b2_kofs);
                #pragma unroll
                for (int i = 0; i < 4; i++)
                    mma16816(acc[i][4], a[i], b2);
            }
        }
    }

    const int lr_base = wm * 64 + (lane >> 2);
    const int nl_base = wn * 40 + 2 * (lane & 3);
    #pragma unroll
    for (int i = 0; i < 4; i++) {
        const int r0 = m0 + lr_base + i * 16;
        #pragma unroll
        for (int j = 0; j < 5; j++) {
            const int ng = n0 + nl_base + j * 8;
            const float2 bi = *(const float2*)(g_bias + ng);   // fold bias here
            *(__half2*)(g_xproj + (size_t)r0 * NP + ng) =
                __floats2half2_rn(acc[i][j][0] + bi.x, acc[i][j][1] + bi.y);
            *(__half2*)(g_xproj + (size_t)(r0 + 8) * NP + ng) =
                __floats2half2_rn(acc[i][j][2] + bi.x, acc[i][j][3] + bi.y);
        }
    }
}

// ---------------- persistent recurrent kernel ----------------
// 128 CTAs (8n x 16m), tile 256x160, 512 threads (4m x 4n warps, warp tile 64x40).
// W_hh resident in smem; c state resident in smem (never touches global);
// A pipeline: 2 stages, wait0 -> sync -> issue(c+1) -> compute(c).
__global__ void __launch_bounds__(512, 1) k_steps(const int* __restrict__ cap,
                                                  const int* __restrict__ cap_len)
{
    extern __shared__ char smem[];
    const uint32_t sb = smem_u32(smem);
    const int tid = threadIdx.x;
    const int wid = tid >> 5;
    const int lane = tid & 31;
    const int wm = wid >> 2;         // 0..3 : 64-row slice
    const int wn = wid & 3;          // 0..3 : 40-col slice
    const int m0 = blockIdx.y * PMT;
    const int n0 = blockIdx.x * PNT;
    const int grp = blockIdx.y;      // m-group id

    int* s_cap = (int*)(smem + PSM_CAP);
    int* s_len = (int*)(smem + PSM_LEN);
    float* s_c = (float*)(smem + PSM_C);

    if (tid < 256) s_len[tid] = cap_len[m0 + tid];
    // zero resident c state
    for (int i = tid; i < 256 * CSTRIDE; i += 512) s_c[i] = 0.f;

    // ---- load resident B (W_hh) tile: 10 planes of 160 rows x 32 cols ----
    const uint32_t sbB = sb + PSM_B;
    for (int u = tid; u < NC * 640; u += 512) {
        const int plane = u / 640;
        const int rem = u - plane * 640;
        const int row = rem >> 2;
        const int cu = rem & 3;
        cp_async16(sbB + plane * PB_PLANE + row * ROWB + cu * 16,
                   g_whhB + (size_t)(n0 + row) * KSEG + plane * 32 + cu * 8);
    }
    cp_commit();
    cp_wait0();
    __syncthreads();

    // A loader geometry: 256 rows x 4 units, 2 units/thread
    const int a_row = tid >> 1;
    const int a_cu  = (tid & 1) * 2;
    uint32_t stA[2];
    stA[0] = sb + PSM_A;
    stA[1] = sb + PSM_A + PA_BYTES;

    // ldmatrix addressing
    const uint32_t a_lrow = (uint32_t)(wm * 64 + (lane & 15)) * ROWB;
    const uint32_t a_kofs = (uint32_t)((lane >> 4) * 16);
    const uint32_t b4_lrow = (uint32_t)(wn * 40 + ((lane >> 4) & 1) * 8 + (lane & 7)) * ROWB;
    const uint32_t b4_kofs = (uint32_t)(((lane >> 3) & 1) * 16);
    const uint32_t b2_lrow = (uint32_t)(wn * 40 + 32 + (lane & 7)) * ROWB;
    const uint32_t b2_kofs = (uint32_t)(((lane >> 3) & 1) * 16);

    const int lr_base = wm * 64 + (lane >> 2);
    const int nl_base = wn * 40 + 2 * (lane & 3);
    const bool odd = lane & 1;
    const int usm_base = wn * 10 + ((lane >> 1) & 1);   // local c unit index base

    unsigned int bar_gen = 0;

    for (int t = 0; t < TT; t++) {
        const int parity = t & 1;
        const __half* Ag = g_h2[parity];
        __half* hout = g_h2[parity ^ 1];

        // tokens + L2 prefetch of gather rows for this step (fp16 rows: 320B/CTA slice)
        if (tid < 256) {
            const int tok = cap[(m0 + tid) * TT + t];
            s_cap[tid] = tok;
            const char* pr = (const char*)(g_xproj + (size_t)tok * NP + n0);
            l2_prefetch(pr);
            l2_prefetch(pr + 128);
            l2_prefetch(pr + 256);
        }
        __syncthreads();

        auto issue_chunk = [&](int c) {
            if (c < NC) {
                const int stage = c & 1;
                const int koff = c * 32;
                const __half* ap = Ag + (size_t)(m0 + a_row) * KSEG + koff + a_cu * 8;
                const uint32_t sa = stA[stage] + a_row * ROWB + a_cu * 16;
                cp_async16(sa, ap);
                cp_async16(sa + 16, ap + 8);
            }
            cp_commit();
        };

        float acc[4][5][4];
        #pragma unroll
        for (int i = 0; i < 4; i++)
            #pragma unroll
            for (int j = 0; j < 5; j++)
                #pragma unroll
                for (int e = 0; e < 4; e++) acc[i][j][e] = 0.f;

        issue_chunk(0);

        for (int c = 0; c < NC; c++) {
            cp_wait0();                 // chunk c landed
            __syncthreads();            // visible to all; stage (c+1)&1 free
            issue_chunk(c + 1);         // prefetch next chunk during compute
            const uint32_t sA = stA[c & 1];
            const uint32_t sB = sbB + c * PB_PLANE;
            #pragma unroll
            for (int k16 = 0; k16 < 2; k16++) {
                uint32_t a[4][4];
                #pragma unroll
                for (int i = 0; i < 4; i++)
                    ldsm_x4(a[i], sA + a_lrow + i * 16 * ROWB + k16 * 32 + a_kofs);
                #pragma unroll
                for (int j2 = 0; j2 < 2; j2++) {
                    uint32_t b4[4];
                    ldsm_x4(b4, sB + b4_lrow + j2 * 16 * ROWB + k16 * 32 + b4_kofs);
                    #pragma unroll
                    for (int i = 0; i < 4; i++) {
                        mma16816(acc[i][2 * j2 + 0], a[i], &b4[0]);
                        mma16816(acc[i][2 * j2 + 1], a[i], &b4[2]);
                    }
                }
                {
                    uint32_t b2[2];
                    ldsm_x2(b2, sB + b2_lrow + k16 * 32 + b2_kofs);
                    #pragma unroll
                    for (int i = 0; i < 4; i++)
                        mma16816(acc[i][4], a[i], b2);
                }
            }
        }

        // ---- fused LSTM epilogue (bias in x_proj; c resident in smem) ----
        #pragma unroll
        for (int i = 0; i < 4; i++) {
            const int lr0 = lr_base + i * 16;
            const int r0 = m0 + lr0, r1 = r0 + 8;
            const int tok0 = s_cap[lr0], tok1 = s_cap[lr0 + 8];
            const int  rme    = odd ? r1 : r0;
            const int  rloc   = odd ? (lr0 + 8) : lr0;
            const bool lastme = odd ? (t == s_len[lr0 + 8] - 1) : (t == s_len[lr0] - 1);
            #pragma unroll
            for (int j = 0; j < 5; j++) {
                const int nl = nl_base + j * 8;
                const int ng = n0 + nl;
                const float2 x0 = __half22float2(*(const __half2*)(g_xproj + (size_t)tok0 * NP + ng));
                const float2 x1 = __half22float2(*(const __half2*)(g_xproj + (size_t)tok1 * NP + ng));
                float v0 = acc[i][j][0] + x0.x;
                float v1 = acc[i][j][1] + x0.y;
                float v2 = acc[i][j][2] + x1.x;
                float v3 = acc[i][j][3] + x1.y;
                float o0 = __shfl_xor_sync(0xffffffff, v0, 1);
                float o1 = __shfl_xor_sync(0xffffffff, v1, 1);
                float o2 = __shfl_xor_sync(0xffffffff, v2, 1);
                float o3 = __shfl_xor_sync(0xffffffff, v3, 1);
                float gi, gf, gg, go;
                if (!odd) { gi = v0; gf = v1; gg = o0; go = o1; }   // row0
                else      { gi = o2; gf = o3; gg = v2; go = v3; }   // row1
                const int u = (ng - (odd ? 2 : 0)) >> 2;            // global unit
                const int usm = usm_base + 2 * j;                   // local unit
                float* cp_ = s_c + rloc * CSTRIDE + usm;
                float I = fsig(gi), F = fsig(gf), G = ftanh(gg), O = fsig(go);
                float cn = F * cp_[0] + I * G;
                float hn = O * ftanh(cn);
                cp_[0] = cn;
                hout[(size_t)rme * KSEG + u] = __float2half_rn(hn);
                if (lastme && u < HH) g_hlast[rme * HH + u] = hn;
            }
        }

        // ---- per-m-group barrier (8 CTAs sharing this m-block) ----
        __threadfence();
        __syncthreads();
        if (tid == 0) {
            unsigned int arrived = atomicAdd(&g_gbar_cnt[grp * 32], 1);
            if (arrived == GRP_CTAS - 1) {
                atomicExch(&g_gbar_cnt[grp * 32], 0);
                __threadfence();
                g_gbar_gen[grp * 32] = bar_gen + 1;
            } else {
                while (g_gbar_gen[grp * 32] == bar_gen) { }
                __threadfence();
            }
        }
        bar_gen++;
        __syncthreads();
    }
}

// ---------------- classifier ----------------
__global__ void k_cls(const float* __restrict__ cls_b, float* __restrict__ out)
{
    int warp = (blockIdx.x * blockDim.x + threadIdx.x) >> 5;
    int lane = threadIdx.x & 31;
    if (warp >= BB) return;
    float s0 = 0.f, s1 = 0.f;
    for (int k = lane; k < HH; k += 32) {
        float hv = g_hlast[warp * HH + k];
        s0 += hv * g_wn[k];
        s1 += hv * g_wn[HH + k];
    }
    #pragma unroll
    for (int o = 16; o; o >>= 1) {
        s0 += __shfl_xor_sync(0xffffffff, s0, o);
        s1 += __shfl_xor_sync(0xffffffff, s1, o);
    }
    if (lane == 0) {
        out[warp * 2 + 0] = s0 + cls_b[0];
        out[warp * 2 + 1] = s1 + cls_b[1];
    }
}

extern "C" void kernel_launch(void* const* d_in, const int* in_sizes, int n_in,
                              void* d_out, int out_size)
{
    const int*   cap     = (const int*)d_in[0];
    const int*   cap_len = (const int*)d_in[1];
    const float* embed_w = (const float*)d_in[2];
    const float* W_ih    = (const float*)d_in[3];
    const float* W_hh    = (const float*)d_in[4];
    const float* b_ih    = (const float*)d_in[5];
    const float* b_hh    = (const float*)d_in[6];
    const float* cls_v   = (const float*)d_in[7];
    const float* cls_g   = (const float*)d_in[8];
    const float* cls_b   = (const float*)d_in[9];
    float* out = (float*)d_out;

    cudaFuncSetAttribute(k_xproj, cudaFuncAttributeMaxDynamicSharedMemorySize, XSMEM_TOTAL);
    cudaFuncSetAttribute(k_steps, cudaFuncAttributeMaxDynamicSharedMemorySize, PSMEM_TOTAL);

    k_prep<<<2048, 256>>>(embed_w, W_ih, W_hh, b_ih, b_hh);
    k_prep_cls<<<1, 64>>>(cls_v, cls_g);

    {   // x_proj = emb @ W_ih^T (+bias), fp16 out
        dim3 grid(NP / XNT, MV / XMT);   // (8, 79)
        k_xproj<<<grid, 256, XSMEM_TOTAL>>>();
    }
    {   // all 32 recurrent steps in one persistent kernel
        dim3 grid(NP / PNT, BB / PMT);   // (8, 16) = 128 CTAs, 1/SM
        k_steps<<<grid, 512, PSMEM_TOTAL>>>(cap, cap_len);
    }
    k_cls<<<512, 256>>>(cls_b, out);
}